// round 1
// baseline (speedup 1.0000x reference)
#include <cuda_runtime.h>
#include <mma.h>
using namespace nvcuda;

// Problem constants
#define B_  4
#define T_  4096
#define D_  1024
#define H_  16
#define R_  256
#define DH_ 64
#define M_  16384   // B_*T_

// Scratch (allocation-free rule: __device__ globals)
__device__ float g_Q[16777216];    // (M, 1024)  q after elu+1
__device__ float g_C[4194304];     // (M, 256)   x@Wd+bd
__device__ float g_KV[33554432];   // (M, 2048)  kv, k-half elu+1'd
__device__ float g_O[16777216];    // (M, 1024)  attention out * z
__device__ float g_ctx[262144];    // (B*H, 64, 64)
__device__ float g_ksum[4096];     // (B*H, 64)

__global__ void zero_kernel() {
    int i = blockIdx.x * blockDim.x + threadIdx.x;
    if (i < 262144) g_ctx[i] = 0.f;
    if (i < 4096)   g_ksum[i] = 0.f;
}

// ---------------------------------------------------------------------------
// Generic tf32 WMMA GEMM: C = act(A(MxK) @ B(KxN) + bias)
// ACT: 0 none, 1 elu(x)+1 on all cols, 2 elu(x)+1 where (col & 127) < 64
// Tiles: 128x128x32, 8 warps (4x2), each warp 32x64 (2x4 frags of 16x16x8)
// ---------------------------------------------------------------------------
#define BM 128
#define BN 128
#define BK 32

template<int ACT>
__global__ __launch_bounds__(256)
void gemm_tf32(const float* __restrict__ A, const float* __restrict__ Bm,
               const float* __restrict__ bias, float* __restrict__ C,
               int Ndim, int Kdim)
{
    __shared__ float As[BM * 36];      // ld 36
    __shared__ float Bs[BK * 132];     // ld 132
    __shared__ float Ep[8 * 320];      // per-warp 16x20 epilogue staging

    const int tid  = threadIdx.x;
    const int warp = tid >> 5;
    const int lane = tid & 31;
    const int wm = warp >> 1;          // 0..3
    const int wn = warp & 1;           // 0..1
    const int row0 = blockIdx.x * BM;
    const int col0 = blockIdx.y * BN;

    wmma::fragment<wmma::accumulator,16,16,8,float> acc[2][4];
    #pragma unroll
    for (int i = 0; i < 2; i++)
        #pragma unroll
        for (int j = 0; j < 4; j++) wmma::fill_fragment(acc[i][j], 0.f);

    for (int k0 = 0; k0 < Kdim; k0 += BK) {
        // Stage A tile (128x32)
        #pragma unroll
        for (int p = 0; p < 4; p++) {
            int idx = tid + p * 256;
            int r = idx >> 3, c4 = (idx & 7) * 4;
            float4 v = *reinterpret_cast<const float4*>(
                A + (size_t)(row0 + r) * Kdim + k0 + c4);
            As[r*36 + c4    ] = v.x;
            As[r*36 + c4 + 1] = v.y;
            As[r*36 + c4 + 2] = v.z;
            As[r*36 + c4 + 3] = v.w;
        }
        // Stage B tile (32x128)
        #pragma unroll
        for (int p = 0; p < 4; p++) {
            int idx = tid + p * 256;
            int r = idx >> 5, c4 = (idx & 31) * 4;
            float4 v = *reinterpret_cast<const float4*>(
                Bm + (size_t)(k0 + r) * Ndim + col0 + c4);
            Bs[r*132 + c4    ] = v.x;
            Bs[r*132 + c4 + 1] = v.y;
            Bs[r*132 + c4 + 2] = v.z;
            Bs[r*132 + c4 + 3] = v.w;
        }
        __syncthreads();

        #pragma unroll
        for (int kk = 0; kk < 4; kk++) {
            wmma::fragment<wmma::matrix_a,16,16,8,wmma::precision::tf32,wmma::row_major> af[2];
            #pragma unroll
            for (int i = 0; i < 2; i++) {
                wmma::load_matrix_sync(af[i], &As[(wm*32 + i*16)*36 + kk*8], 36);
                #pragma unroll
                for (int e = 0; e < af[i].num_elements; e++)
                    af[i].x[e] = wmma::__float_to_tf32(af[i].x[e]);
            }
            #pragma unroll
            for (int j = 0; j < 4; j++) {
                wmma::fragment<wmma::matrix_b,16,16,8,wmma::precision::tf32,wmma::row_major> bf;
                wmma::load_matrix_sync(bf, &Bs[(kk*8)*132 + wn*64 + j*16], 132);
                #pragma unroll
                for (int e = 0; e < bf.num_elements; e++)
                    bf.x[e] = wmma::__float_to_tf32(bf.x[e]);
                #pragma unroll
                for (int i = 0; i < 2; i++)
                    wmma::mma_sync(acc[i][j], af[i], bf, acc[i][j]);
            }
        }
        __syncthreads();
    }

    // Epilogue: bias + optional elu+1, staged through shared per warp
    float* ep = &Ep[warp * 320];
    #pragma unroll
    for (int i = 0; i < 2; i++) {
        #pragma unroll
        for (int j = 0; j < 4; j++) {
            __syncwarp();
            wmma::store_matrix_sync(ep, acc[i][j], 20, wmma::mem_row_major);
            __syncwarp();
            int gr0 = row0 + wm*32 + i*16;
            int gc0 = col0 + wn*64 + j*16;
            #pragma unroll
            for (int t = lane; t < 256; t += 32) {
                int rr = t >> 4, cc = t & 15;
                int gc = gc0 + cc;
                float v = ep[rr*20 + cc] + bias[gc];
                if (ACT == 1) {
                    v = (v > 0.f) ? v + 1.f : __expf(v);
                } else if (ACT == 2) {
                    if ((gc & 127) < 64) v = (v > 0.f) ? v + 1.f : __expf(v);
                }
                C[(size_t)(gr0 + rr) * Ndim + gc] = v;
            }
        }
    }
}

// ---------------------------------------------------------------------------
// ctx[b,h] = sum_t k[t,:]^T v[t,:]  (64x64, K=T split 8 ways, atomicAdd reduce)
// also ksum[b,h,d] = sum_t k[t,d]
// ---------------------------------------------------------------------------
__global__ __launch_bounds__(128)
void ctx_kernel()
{
    const int bh = blockIdx.x;           // 0..63
    const int split = blockIdx.y;        // 0..7
    const int b = bh >> 4, h = bh & 15;
    const float* Kb = g_KV + (size_t)b * T_ * 2048 + h * 128;
    const float* Vb = Kb + 64;
    const int tid  = threadIdx.x;
    const int warp = tid >> 5, lane = tid & 31;
    const int tbase = split * 512 + warp * 128;

    wmma::fragment<wmma::accumulator,16,16,8,float> acc[4][4];
    #pragma unroll
    for (int i = 0; i < 4; i++)
        #pragma unroll
        for (int j = 0; j < 4; j++) wmma::fill_fragment(acc[i][j], 0.f);

    for (int ks = 0; ks < 16; ks++) {
        int t0 = tbase + ks * 8;
        // A = K^T (64 x 8): col_major view of k rows, ld = 2048
        wmma::fragment<wmma::matrix_a,16,16,8,wmma::precision::tf32,wmma::col_major> af[4];
        #pragma unroll
        for (int i = 0; i < 4; i++) {
            wmma::load_matrix_sync(af[i], Kb + (size_t)t0 * 2048 + i*16, 2048);
            #pragma unroll
            for (int e = 0; e < af[i].num_elements; e++)
                af[i].x[e] = wmma::__float_to_tf32(af[i].x[e]);
        }
        #pragma unroll
        for (int j = 0; j < 4; j++) {
            wmma::fragment<wmma::matrix_b,16,16,8,wmma::precision::tf32,wmma::row_major> bf;
            wmma::load_matrix_sync(bf, Vb + (size_t)t0 * 2048 + j*16, 2048);
            #pragma unroll
            for (int e = 0; e < bf.num_elements; e++)
                bf.x[e] = wmma::__float_to_tf32(bf.x[e]);
            #pragma unroll
            for (int i = 0; i < 4; i++)
                wmma::mma_sync(acc[i][j], af[i], bf, acc[i][j]);
        }
    }

    __shared__ float ep[4][320];
    float* buf  = ep[warp];
    float* ctxp = g_ctx + bh * 4096;
    #pragma unroll
    for (int i = 0; i < 4; i++) {
        #pragma unroll
        for (int j = 0; j < 4; j++) {
            __syncwarp();
            wmma::store_matrix_sync(buf, acc[i][j], 20, wmma::mem_row_major);
            __syncwarp();
            for (int t = lane; t < 256; t += 32) {
                int rr = t >> 4, cc = t & 15;
                atomicAdd(&ctxp[(i*16 + rr)*64 + j*16 + cc], buf[rr*20 + cc]);
            }
        }
    }

    // ksum partial for this split
    int d = tid & 63, grp = tid >> 6;    // 2 groups of 64
    float s = 0.f;
    int tstart = split * 512 + grp * 256;
    for (int t = tstart; t < tstart + 256; t++)
        s += Kb[(size_t)t * 2048 + d];
    atomicAdd(&g_ksum[bh * 64 + d], s);
}

// ---------------------------------------------------------------------------
// out[b,t,h,:] = (q[b,t,h,:] @ ctx[b,h]) * 1/(q·ksum + 1e-6)
// 64-token tiles; ksum rides as column 64 of an extended 64x80 B matrix.
// ---------------------------------------------------------------------------
__global__ __launch_bounds__(128)
void attn_out_kernel()
{
    const int bh = blockIdx.x;           // 0..63
    const int tt = blockIdx.y;           // 0..63 token tile
    const int b = bh >> 4, h = bh & 15;
    const int tid = threadIdx.x;
    const int warp = tid >> 5, lane = tid & 31;

    __shared__ float Qs[64 * 68];        // 64 tok x 64 d, ld 68
    __shared__ float Cs[64 * 84];        // 64 d x 80 cols (64 ctx + ksum + pad), ld 84

    const float* Qb = g_Q + (size_t)(b * T_ + tt * 64) * 1024 + h * 64;
    #pragma unroll
    for (int p = 0; p < 8; p++) {
        int idx = tid + p * 128;         // 1024 float4
        int r = idx >> 4, c4 = (idx & 15) * 4;
        float4 v = *reinterpret_cast<const float4*>(Qb + (size_t)r * 1024 + c4);
        Qs[r*68 + c4    ] = v.x;
        Qs[r*68 + c4 + 1] = v.y;
        Qs[r*68 + c4 + 2] = v.z;
        Qs[r*68 + c4 + 3] = v.w;
    }
    for (int i = tid; i < 64 * 84; i += 128) Cs[i] = 0.f;
    __syncthreads();
    const float* cp = g_ctx + bh * 4096;
    for (int i = tid; i < 4096; i += 128) {
        int d = i >> 6, e = i & 63;
        Cs[d*84 + e] = cp[i];
    }
    if (tid < 64) Cs[tid*84 + 64] = g_ksum[bh * 64 + tid];
    __syncthreads();

    wmma::fragment<wmma::accumulator,16,16,8,float> acc[5];
    #pragma unroll
    for (int j = 0; j < 5; j++) wmma::fill_fragment(acc[j], 0.f);

    #pragma unroll
    for (int k = 0; k < 8; k++) {
        wmma::fragment<wmma::matrix_a,16,16,8,wmma::precision::tf32,wmma::row_major> af;
        wmma::load_matrix_sync(af, &Qs[(warp*16)*68 + k*8], 68);
        #pragma unroll
        for (int e = 0; e < af.num_elements; e++)
            af.x[e] = wmma::__float_to_tf32(af.x[e]);
        #pragma unroll
        for (int j = 0; j < 5; j++) {
            wmma::fragment<wmma::matrix_b,16,16,8,wmma::precision::tf32,wmma::row_major> bf;
            wmma::load_matrix_sync(bf, &Cs[(k*8)*84 + j*16], 84);
            #pragma unroll
            for (int e = 0; e < bf.num_elements; e++)
                bf.x[e] = wmma::__float_to_tf32(bf.x[e]);
            wmma::mma_sync(acc[j], af, bf, acc[j]);
        }
    }
    __syncthreads();   // everyone done reading Cs/Qs before reuse

    float* buf = &Cs[(warp*16) * 84];
    #pragma unroll
    for (int j = 0; j < 5; j++)
        wmma::store_matrix_sync(buf + j*16, acc[j], 84, wmma::mem_row_major);
    __syncwarp();

    float* Ob = g_O + (size_t)(b * T_ + tt * 64 + warp * 16) * 1024 + h * 64;
    for (int t = lane; t < 16 * 64; t += 32) {
        int rr = t >> 6, cc = t & 63;
        float z = 1.f / (buf[rr*84 + 64] + 1e-6f);
        Ob[(size_t)rr * 1024 + cc] = buf[rr*84 + cc] * z;
    }
}

// ---------------------------------------------------------------------------
extern "C" void kernel_launch(void* const* d_in, const int* in_sizes, int n_in,
                              void* d_out, int out_size)
{
    const float* x  = (const float*)d_in[0];
    const float* Wq = (const float*)d_in[1];
    const float* bq = (const float*)d_in[2];
    const float* Wd = (const float*)d_in[3];
    const float* bd = (const float*)d_in[4];
    const float* Wu = (const float*)d_in[5];
    const float* bu = (const float*)d_in[6];
    const float* Wo = (const float*)d_in[7];
    const float* bo = (const float*)d_in[8];
    float* out = (float*)d_out;

    void *pQ, *pC, *pKV, *pO;
    cudaGetSymbolAddress(&pQ,  g_Q);
    cudaGetSymbolAddress(&pC,  g_C);
    cudaGetSymbolAddress(&pKV, g_KV);
    cudaGetSymbolAddress(&pO,  g_O);

    zero_kernel<<<1024, 256>>>();

    // Q = elu(x@Wq + bq) + 1
    gemm_tf32<1><<<dim3(M_/BM, 1024/BN), 256>>>(x, Wq, bq, (float*)pQ, 1024, 1024);
    // C = x@Wd + bd
    gemm_tf32<0><<<dim3(M_/BM,  256/BN), 256>>>(x, Wd, bd, (float*)pC,  256, 1024);
    // KV = C@Wu + bu, elu+1 on k half of each head
    gemm_tf32<2><<<dim3(M_/BM, 2048/BN), 256>>>((const float*)pC, Wu, bu, (float*)pKV, 2048, 256);

    ctx_kernel<<<dim3(64, 8), 128>>>();
    attn_out_kernel<<<dim3(64, 64), 128>>>();

    // out = O@Wo + bo
    gemm_tf32<0><<<dim3(M_/BM, 1024/BN), 256>>>((const float*)pO, Wo, bo, out, 1024, 1024);
}

// round 3
// speedup vs baseline: 1.2020x; 1.2020x over previous
#include <cuda_runtime.h>
#include <cstdint>
#include <mma.h>
using namespace nvcuda;

// Problem constants
#define B_  4
#define T_  4096
#define D_  1024
#define H_  16
#define R_  256
#define DH_ 64
#define M_  16384   // B_*T_

// Scratch (allocation-free rule: __device__ globals)
__device__ float g_Q[16777216];    // (M, 1024)  q after elu+1
__device__ float g_C[4194304];     // (M, 256)   x@Wd+bd
__device__ float g_KV[33554432];   // (M, 2048)  kv, k-half elu+1'd
__device__ float g_O[16777216];    // (M, 1024)  attention out * z
__device__ float g_ctx[262144];    // (B*H, 64, 64)
__device__ float g_ksum[4096];     // (B*H, 64)

__global__ void zero_kernel() {
    int i = blockIdx.x * blockDim.x + threadIdx.x;
    if (i < 262144) g_ctx[i] = 0.f;
    if (i < 4096)   g_ksum[i] = 0.f;
}

// ---------------------------------------------------------------------------
// cp.async helpers (16B)
// ---------------------------------------------------------------------------
__device__ __forceinline__ void cp16(void* smem_dst, const void* gmem_src) {
    unsigned s = (unsigned)__cvta_generic_to_shared(smem_dst);
    asm volatile("cp.async.cg.shared.global [%0], [%1], 16;\n" :: "r"(s), "l"(gmem_src));
}
__device__ __forceinline__ void cp_commit() {
    asm volatile("cp.async.commit_group;\n" ::: "memory");
}
template<int N>
__device__ __forceinline__ void cp_wait() {
    asm volatile("cp.async.wait_group %0;\n" :: "n"(N) : "memory");
}

// ---------------------------------------------------------------------------
// tf32 WMMA GEMM, 3-stage cp.async pipeline.
// C = act(A(MxK) @ B(KxN) + bias)
// ACT: 0 none, 1 elu(x)+1 on all cols, 2 elu(x)+1 where (col & 127) < 64
// Tiles: 128x128x32, 8 warps (4x2), each warp 32x64 (2x4 frags of 16x16x8)
// Dynamic smem: 3 stages of A[128x36] + B[32x132]  (~106 KB)
// ---------------------------------------------------------------------------
#define BM 128
#define BN 128
#define BK 32
#define LDA 36
#define LDB 132
#define STAGE_A (BM * LDA)        // 4608 floats
#define STAGE_B (BK * LDB)        // 4224 floats
#define SMEM_FLOATS (3 * (STAGE_A + STAGE_B))   // 26496 floats = 105984 B

template<int ACT>
__global__ __launch_bounds__(256)
void gemm_tf32(const float* __restrict__ A, const float* __restrict__ Bm,
               const float* __restrict__ bias, float* __restrict__ C,
               int Ndim, int Kdim)
{
    extern __shared__ float sm[];
    float* Asm = sm;                      // 3 * STAGE_A
    float* Bsm = sm + 3 * STAGE_A;        // 3 * STAGE_B

    const int tid  = threadIdx.x;
    const int warp = tid >> 5;
    const int lane = tid & 31;
    const int wm = warp >> 1;             // 0..3
    const int wn = warp & 1;              // 0..1
    const int row0 = blockIdx.x * BM;
    const int col0 = blockIdx.y * BN;

    const int Ktiles = Kdim / BK;

    // per-thread staging coords
    const int a_r = tid >> 3, a_c = (tid & 7) * 4;     // + p*32 rows
    const int b_r = tid >> 5, b_c = (tid & 31) * 4;    // + p*8 rows

    auto issue = [&](int stage, int kt) {
        float* as = Asm + stage * STAGE_A;
        float* bs = Bsm + stage * STAGE_B;
        const float* Ag = A + (size_t)row0 * Kdim + (size_t)kt * BK;
        const float* Bg = Bm + (size_t)kt * BK * Ndim + col0;
        #pragma unroll
        for (int p = 0; p < 4; p++) {
            int r = a_r + p * 32;
            cp16(&as[r * LDA + a_c], Ag + (size_t)r * Kdim + a_c);
        }
        #pragma unroll
        for (int p = 0; p < 4; p++) {
            int r = b_r + p * 8;
            cp16(&bs[r * LDB + b_c], Bg + (size_t)r * Ndim + b_c);
        }
    };

    wmma::fragment<wmma::accumulator,16,16,8,float> acc[2][4];
    #pragma unroll
    for (int i = 0; i < 2; i++)
        #pragma unroll
        for (int j = 0; j < 4; j++) wmma::fill_fragment(acc[i][j], 0.f);

    issue(0, 0); cp_commit();
    issue(1, 1); cp_commit();

    int stage = 0;
    for (int kt = 0; kt < Ktiles; kt++) {
        cp_wait<1>();
        __syncthreads();

        if (kt + 2 < Ktiles) issue((stage + 2 >= 3) ? stage - 1 : stage + 2, kt + 2);
        cp_commit();

        const float* as = Asm + stage * STAGE_A;
        const float* bs = Bsm + stage * STAGE_B;

        #pragma unroll
        for (int kk = 0; kk < 4; kk++) {
            wmma::fragment<wmma::matrix_a,16,16,8,wmma::precision::tf32,wmma::row_major> af[2];
            #pragma unroll
            for (int i = 0; i < 2; i++) {
                wmma::load_matrix_sync(af[i], &as[(wm*32 + i*16)*LDA + kk*8], LDA);
                #pragma unroll
                for (int e = 0; e < af[i].num_elements; e++)
                    af[i].x[e] = wmma::__float_to_tf32(af[i].x[e]);
            }
            #pragma unroll
            for (int j = 0; j < 4; j++) {
                wmma::fragment<wmma::matrix_b,16,16,8,wmma::precision::tf32,wmma::row_major> bf;
                wmma::load_matrix_sync(bf, &bs[(kk*8)*LDB + wn*64 + j*16], LDB);
                #pragma unroll
                for (int e = 0; e < bf.num_elements; e++)
                    bf.x[e] = wmma::__float_to_tf32(bf.x[e]);
                #pragma unroll
                for (int i = 0; i < 2; i++)
                    wmma::mma_sync(acc[i][j], af[i], bf, acc[i][j]);
            }
        }
        stage = (stage + 1 == 3) ? 0 : stage + 1;
    }

    // Epilogue: bulk store to reused smem, then float4 global stores.
    __syncthreads();
    float* ep = sm + warp * (32 * 68);    // 2176 floats/warp, 8 warps = 17408 < 26496
    #pragma unroll
    for (int i = 0; i < 2; i++)
        #pragma unroll
        for (int j = 0; j < 4; j++)
            wmma::store_matrix_sync(ep + (i*16)*68 + j*16, acc[i][j], 68,
                                    wmma::mem_row_major);
    __syncwarp();

    const int gr0 = row0 + wm * 32;
    const int gc0 = col0 + wn * 64;
    #pragma unroll
    for (int idx = lane; idx < 512; idx += 32) {   // 32 rows x 16 float4
        int rr = idx >> 4, c4 = (idx & 15) * 4;
        int gc = gc0 + c4;
        float4 v = *reinterpret_cast<const float4*>(&ep[rr*68 + c4]);
        float4 bb = *reinterpret_cast<const float4*>(&bias[gc]);
        v.x += bb.x; v.y += bb.y; v.z += bb.z; v.w += bb.w;
        if (ACT == 1 || (ACT == 2 && (gc & 127) < 64)) {
            v.x = (v.x > 0.f) ? v.x + 1.f : __expf(v.x);
            v.y = (v.y > 0.f) ? v.y + 1.f : __expf(v.y);
            v.z = (v.z > 0.f) ? v.z + 1.f : __expf(v.z);
            v.w = (v.w > 0.f) ? v.w + 1.f : __expf(v.w);
        }
        *reinterpret_cast<float4*>(&C[(size_t)(gr0 + rr) * Ndim + gc]) = v;
    }
}

// ---------------------------------------------------------------------------
// ctx[b,h] = sum_t k[t,:]^T v[t,:]  (64x64, K=T split 8 ways, atomicAdd reduce)
// also ksum[b,h,d] = sum_t k[t,d]
// ---------------------------------------------------------------------------
__global__ __launch_bounds__(128)
void ctx_kernel()
{
    const int bh = blockIdx.x;           // 0..63
    const int split = blockIdx.y;        // 0..7
    const int b = bh >> 4, h = bh & 15;
    const float* Kb = g_KV + (size_t)b * T_ * 2048 + h * 128;
    const float* Vb = Kb + 64;
    const int tid  = threadIdx.x;
    const int warp = tid >> 5, lane = tid & 31;
    const int tbase = split * 512 + warp * 128;

    wmma::fragment<wmma::accumulator,16,16,8,float> acc[4][4];
    #pragma unroll
    for (int i = 0; i < 4; i++)
        #pragma unroll
        for (int j = 0; j < 4; j++) wmma::fill_fragment(acc[i][j], 0.f);

    for (int ks = 0; ks < 16; ks++) {
        int t0 = tbase + ks * 8;
        wmma::fragment<wmma::matrix_a,16,16,8,wmma::precision::tf32,wmma::col_major> af[4];
        #pragma unroll
        for (int i = 0; i < 4; i++) {
            wmma::load_matrix_sync(af[i], Kb + (size_t)t0 * 2048 + i*16, 2048);
            #pragma unroll
            for (int e = 0; e < af[i].num_elements; e++)
                af[i].x[e] = wmma::__float_to_tf32(af[i].x[e]);
        }
        #pragma unroll
        for (int j = 0; j < 4; j++) {
            wmma::fragment<wmma::matrix_b,16,16,8,wmma::precision::tf32,wmma::row_major> bf;
            wmma::load_matrix_sync(bf, Vb + (size_t)t0 * 2048 + j*16, 2048);
            #pragma unroll
            for (int e = 0; e < bf.num_elements; e++)
                bf.x[e] = wmma::__float_to_tf32(bf.x[e]);
            #pragma unroll
            for (int i = 0; i < 4; i++)
                wmma::mma_sync(acc[i][j], af[i], bf, acc[i][j]);
        }
    }

    __shared__ float ep[4][320];
    float* buf  = ep[warp];
    float* ctxp = g_ctx + bh * 4096;
    #pragma unroll
    for (int i = 0; i < 4; i++) {
        #pragma unroll
        for (int j = 0; j < 4; j++) {
            __syncwarp();
            wmma::store_matrix_sync(buf, acc[i][j], 20, wmma::mem_row_major);
            __syncwarp();
            for (int t = lane; t < 256; t += 32) {
                int rr = t >> 4, cc = t & 15;
                atomicAdd(&ctxp[(i*16 + rr)*64 + j*16 + cc], buf[rr*20 + cc]);
            }
        }
    }

    // ksum partial for this split
    int d = tid & 63, grp = tid >> 6;    // 2 groups of 64
    float s = 0.f;
    int tstart = split * 512 + grp * 256;
    for (int t = tstart; t < tstart + 256; t++)
        s += Kb[(size_t)t * 2048 + d];
    atomicAdd(&g_ksum[bh * 64 + d], s);
}

// ---------------------------------------------------------------------------
// out[b,t,h,:] = (q[b,t,h,:] @ ctx[b,h]) * 1/(q·ksum + 1e-6)
// 64-token tiles; ksum rides as column 64 of an extended 64x80 B matrix.
// ---------------------------------------------------------------------------
__global__ __launch_bounds__(128)
void attn_out_kernel()
{
    const int bh = blockIdx.x;           // 0..63
    const int tt = blockIdx.y;           // 0..63 token tile
    const int b = bh >> 4, h = bh & 15;
    const int tid = threadIdx.x;
    const int warp = tid >> 5, lane = tid & 31;

    __shared__ float Qs[64 * 68];        // 64 tok x 64 d, ld 68
    __shared__ float Cs[64 * 84];        // 64 d x 80 cols (64 ctx + ksum + pad), ld 84

    const float* Qb = g_Q + (size_t)(b * T_ + tt * 64) * 1024 + h * 64;
    #pragma unroll
    for (int p = 0; p < 8; p++) {
        int idx = tid + p * 128;         // 1024 float4
        int r = idx >> 4, c4 = (idx & 15) * 4;
        float4 v = *reinterpret_cast<const float4*>(Qb + (size_t)r * 1024 + c4);
        Qs[r*68 + c4    ] = v.x;
        Qs[r*68 + c4 + 1] = v.y;
        Qs[r*68 + c4 + 2] = v.z;
        Qs[r*68 + c4 + 3] = v.w;
    }
    for (int i = tid; i < 64 * 84; i += 128) Cs[i] = 0.f;
    __syncthreads();
    const float* cp = g_ctx + bh * 4096;
    for (int i = tid; i < 4096; i += 128) {
        int d = i >> 6, e = i & 63;
        Cs[d*84 + e] = cp[i];
    }
    if (tid < 64) Cs[tid*84 + 64] = g_ksum[bh * 64 + tid];
    __syncthreads();

    wmma::fragment<wmma::accumulator,16,16,8,float> acc[5];
    #pragma unroll
    for (int j = 0; j < 5; j++) wmma::fill_fragment(acc[j], 0.f);

    #pragma unroll
    for (int k = 0; k < 8; k++) {
        wmma::fragment<wmma::matrix_a,16,16,8,wmma::precision::tf32,wmma::row_major> af;
        wmma::load_matrix_sync(af, &Qs[(warp*16)*68 + k*8], 68);
        #pragma unroll
        for (int e = 0; e < af.num_elements; e++)
            af.x[e] = wmma::__float_to_tf32(af.x[e]);
        #pragma unroll
        for (int j = 0; j < 5; j++) {
            wmma::fragment<wmma::matrix_b,16,16,8,wmma::precision::tf32,wmma::row_major> bf;
            wmma::load_matrix_sync(bf, &Cs[(k*8)*84 + j*16], 84);
            #pragma unroll
            for (int e = 0; e < bf.num_elements; e++)
                bf.x[e] = wmma::__float_to_tf32(bf.x[e]);
            wmma::mma_sync(acc[j], af, bf, acc[j]);
        }
    }
    __syncthreads();   // everyone done reading Cs/Qs before reuse

    float* buf = &Cs[(warp*16) * 84];
    #pragma unroll
    for (int j = 0; j < 5; j++)
        wmma::store_matrix_sync(buf + j*16, acc[j], 84, wmma::mem_row_major);
    __syncwarp();

    float* Ob = g_O + (size_t)(b * T_ + tt * 64 + warp * 16) * 1024 + h * 64;
    for (int t = lane; t < 16 * 64; t += 32) {
        int rr = t >> 6, cc = t & 63;
        float z = 1.f / (buf[rr*84 + 64] + 1e-6f);
        Ob[(size_t)rr * 1024 + cc] = buf[rr*84 + cc] * z;
    }
}

// ---------------------------------------------------------------------------
extern "C" void kernel_launch(void* const* d_in, const int* in_sizes, int n_in,
                              void* d_out, int out_size)
{
    const float* x  = (const float*)d_in[0];
    const float* Wq = (const float*)d_in[1];
    const float* bq = (const float*)d_in[2];
    const float* Wd = (const float*)d_in[3];
    const float* bd = (const float*)d_in[4];
    const float* Wu = (const float*)d_in[5];
    const float* bu = (const float*)d_in[6];
    const float* Wo = (const float*)d_in[7];
    const float* bo = (const float*)d_in[8];
    float* out = (float*)d_out;

    void *pQ, *pC, *pKV, *pO;
    cudaGetSymbolAddress(&pQ,  g_Q);
    cudaGetSymbolAddress(&pC,  g_C);
    cudaGetSymbolAddress(&pKV, g_KV);
    cudaGetSymbolAddress(&pO,  g_O);

    const int smem_bytes = SMEM_FLOATS * sizeof(float);   // 105984
    cudaFuncSetAttribute(gemm_tf32<0>, cudaFuncAttributeMaxDynamicSharedMemorySize, smem_bytes);
    cudaFuncSetAttribute(gemm_tf32<1>, cudaFuncAttributeMaxDynamicSharedMemorySize, smem_bytes);
    cudaFuncSetAttribute(gemm_tf32<2>, cudaFuncAttributeMaxDynamicSharedMemorySize, smem_bytes);

    zero_kernel<<<1024, 256>>>();

    // Q = elu(x@Wq + bq) + 1
    gemm_tf32<1><<<dim3(M_/BM, 1024/BN), 256, smem_bytes>>>(x, Wq, bq, (float*)pQ, 1024, 1024);
    // C = x@Wd + bd
    gemm_tf32<0><<<dim3(M_/BM,  256/BN), 256, smem_bytes>>>(x, Wd, bd, (float*)pC,  256, 1024);
    // KV = C@Wu + bu, elu+1 on k half of each head
    gemm_tf32<2><<<dim3(M_/BM, 2048/BN), 256, smem_bytes>>>((const float*)pC, Wu, bu, (float*)pKV, 2048, 256);

    ctx_kernel<<<dim3(64, 8), 128>>>();
    attn_out_kernel<<<dim3(64, 64), 128>>>();

    // out = O@Wo + bo
    gemm_tf32<0><<<dim3(M_/BM, 1024/BN), 256, smem_bytes>>>((const float*)pO, Wo, bo, out, 1024, 1024);
}

// round 5
// speedup vs baseline: 1.3797x; 1.1478x over previous
#include <cuda_runtime.h>
#include <cstdint>
#include <mma.h>
using namespace nvcuda;

// Problem constants
#define B_  4
#define T_  4096
#define D_  1024
#define H_  16
#define R_  256
#define DH_ 64
#define M_  16384   // B_*T_

// Scratch (allocation-free rule: __device__ globals)
__device__ float g_X [16777216];   // x tf32-rounded
__device__ float g_Q [16777216];   // (M,1024) q after elu+1, tf32-rounded
__device__ float g_C [4194304];    // (M,256)  x@Wd+bd, tf32-rounded
__device__ float g_KV[33554432];   // (M,2048) kv, k-half elu+1'd (fp32)
__device__ float g_O [16777216];   // (M,1024) attention out * z, tf32-rounded
__device__ float g_ctx[262144];    // (B*H,64,64)
__device__ float g_ksum[4096];     // (B*H,64)
__device__ float g_WqR[1048576];   // rounded weights (same layout as inputs)
__device__ float g_WdR[262144];
__device__ float g_WuR[524288];
__device__ float g_WoR[1048576];

__global__ void zero_kernel() {
    int i = blockIdx.x * blockDim.x + threadIdx.x;
    if (i < 262144) g_ctx[i] = 0.f;
    if (i < 4096)   g_ksum[i] = 0.f;
}

// elementwise tf32-round copy (float4); n4 = element count / 4
__global__ void round_copy(const float* __restrict__ src, float* __restrict__ dst, int n4) {
    int i = blockIdx.x * blockDim.x + threadIdx.x;
    if (i >= n4) return;
    float4 v = reinterpret_cast<const float4*>(src)[i];
    v.x = wmma::__float_to_tf32(v.x);
    v.y = wmma::__float_to_tf32(v.y);
    v.z = wmma::__float_to_tf32(v.z);
    v.w = wmma::__float_to_tf32(v.w);
    reinterpret_cast<float4*>(dst)[i] = v;
}

// ---------------------------------------------------------------------------
// cp.async helpers (16B)
// ---------------------------------------------------------------------------
__device__ __forceinline__ void cp16(void* smem_dst, const void* gmem_src) {
    unsigned s = (unsigned)__cvta_generic_to_shared(smem_dst);
    asm volatile("cp.async.cg.shared.global [%0], [%1], 16;\n" :: "r"(s), "l"(gmem_src));
}
__device__ __forceinline__ void cp_commit() {
    asm volatile("cp.async.commit_group;\n" ::: "memory");
}
template<int N>
__device__ __forceinline__ void cp_wait() {
    asm volatile("cp.async.wait_group %0;\n" :: "n"(N) : "memory");
}

// ---------------------------------------------------------------------------
// tf32 WMMA GEMM, 2-stage cp.async double buffer, 2 CTAs/SM.
// All operands MUST be pre-rounded to tf32 (no in-loop conversion: HMMA's
// internal truncation is identity on rounded values).
// C = act(A(MxK) @ B(KxN) + bias)
// ACT: 0 none, 1 elu+1 all cols, 2 elu+1 where (col&127)<64
// ROUND: tf32-round the output (when it feeds another GEMM as operand)
// Tiles: 128x128x32, 8 warps (4x2), warp tile 32x64
// ---------------------------------------------------------------------------
#define BM 128
#define BN 128
#define BK 32
#define LDA 36
#define LDB 132
#define STAGE_A (BM * LDA)        // 4608 floats
#define STAGE_B (BK * LDB)        // 4224 floats
#define SMEM_FLOATS (2 * (STAGE_A + STAGE_B))   // 17664 floats = 70656 B

template<int ACT, int ROUND>
__global__ __launch_bounds__(256, 2)
void gemm_tf32(const float* __restrict__ A, const float* __restrict__ Bm,
               const float* __restrict__ bias, float* __restrict__ C,
               int Ndim, int Kdim)
{
    extern __shared__ float sm[];
    float* Asm = sm;                      // 2 * STAGE_A
    float* Bsm = sm + 2 * STAGE_A;        // 2 * STAGE_B

    const int tid  = threadIdx.x;
    const int warp = tid >> 5;
    const int lane = tid & 31;
    const int wm = warp >> 1;             // 0..3
    const int wn = warp & 1;              // 0..1
    const int row0 = blockIdx.x * BM;
    const int col0 = blockIdx.y * BN;

    const int Ktiles = Kdim / BK;

    const int a_r = tid >> 3, a_c = (tid & 7) * 4;     // + p*32 rows
    const int b_r = tid >> 5, b_c = (tid & 31) * 4;    // + p*8 rows

    auto issue = [&](int stage, int kt) {
        float* as = Asm + stage * STAGE_A;
        float* bs = Bsm + stage * STAGE_B;
        const float* Ag = A + (size_t)row0 * Kdim + (size_t)kt * BK;
        const float* Bg = Bm + (size_t)kt * BK * Ndim + col0;
        #pragma unroll
        for (int p = 0; p < 4; p++) {
            int r = a_r + p * 32;
            cp16(&as[r * LDA + a_c], Ag + (size_t)r * Kdim + a_c);
        }
        #pragma unroll
        for (int p = 0; p < 4; p++) {
            int r = b_r + p * 8;
            cp16(&bs[r * LDB + b_c], Bg + (size_t)r * Ndim + b_c);
        }
    };

    wmma::fragment<wmma::accumulator,16,16,8,float> acc[2][4];
    #pragma unroll
    for (int i = 0; i < 2; i++)
        #pragma unroll
        for (int j = 0; j < 4; j++) wmma::fill_fragment(acc[i][j], 0.f);

    issue(0, 0); cp_commit();

    for (int kt = 0; kt < Ktiles; kt++) {
        if (kt + 1 < Ktiles) { issue((kt + 1) & 1, kt + 1); cp_commit(); }
        cp_wait<1>();
        __syncthreads();

        const float* as = Asm + (kt & 1) * STAGE_A;
        const float* bs = Bsm + (kt & 1) * STAGE_B;

        #pragma unroll
        for (int kk = 0; kk < 4; kk++) {
            wmma::fragment<wmma::matrix_a,16,16,8,wmma::precision::tf32,wmma::row_major> af[2];
            #pragma unroll
            for (int i = 0; i < 2; i++)
                wmma::load_matrix_sync(af[i], &as[(wm*32 + i*16)*LDA + kk*8], LDA);
            #pragma unroll
            for (int j = 0; j < 4; j++) {
                wmma::fragment<wmma::matrix_b,16,16,8,wmma::precision::tf32,wmma::row_major> bf;
                wmma::load_matrix_sync(bf, &bs[(kk*8)*LDB + wn*64 + j*16], LDB);
                #pragma unroll
                for (int i = 0; i < 2; i++)
                    wmma::mma_sync(acc[i][j], af[i], bf, acc[i][j]);
            }
        }
        __syncthreads();
    }

    // Epilogue: bulk store to reused smem, then float4 global stores.
    float* ep = sm + warp * (32 * 68);    // 2176 floats/warp * 8 = 17408 < 17664
    #pragma unroll
    for (int i = 0; i < 2; i++)
        #pragma unroll
        for (int j = 0; j < 4; j++)
            wmma::store_matrix_sync(ep + (i*16)*68 + j*16, acc[i][j], 68,
                                    wmma::mem_row_major);
    __syncwarp();

    const int gr0 = row0 + wm * 32;
    const int gc0 = col0 + wn * 64;
    #pragma unroll
    for (int idx = lane; idx < 512; idx += 32) {   // 32 rows x 16 float4
        int rr = idx >> 4, c4 = (idx & 15) * 4;
        int gc = gc0 + c4;
        float4 v = *reinterpret_cast<const float4*>(&ep[rr*68 + c4]);
        float4 bb = *reinterpret_cast<const float4*>(&bias[gc]);
        v.x += bb.x; v.y += bb.y; v.z += bb.z; v.w += bb.w;
        if (ACT == 1 || (ACT == 2 && (gc & 127) < 64)) {
            v.x = (v.x > 0.f) ? v.x + 1.f : __expf(v.x);
            v.y = (v.y > 0.f) ? v.y + 1.f : __expf(v.y);
            v.z = (v.z > 0.f) ? v.z + 1.f : __expf(v.z);
            v.w = (v.w > 0.f) ? v.w + 1.f : __expf(v.w);
        }
        if (ROUND) {
            v.x = wmma::__float_to_tf32(v.x);
            v.y = wmma::__float_to_tf32(v.y);
            v.z = wmma::__float_to_tf32(v.z);
            v.w = wmma::__float_to_tf32(v.w);
        }
        *reinterpret_cast<float4*>(&C[(size_t)(gr0 + rr) * Ndim + gc]) = v;
    }
}

// ---------------------------------------------------------------------------
// ctx[b,h] = sum_t k[t,:]^T v[t,:]  (64x64, split-K atomics) + ksum
// ---------------------------------------------------------------------------
__global__ __launch_bounds__(128)
void ctx_kernel()
{
    const int bh = blockIdx.x;           // 0..63
    const int split = blockIdx.y;        // 0..7
    const int b = bh >> 4, h = bh & 15;
    const float* Kb = g_KV + (size_t)b * T_ * 2048 + h * 128;
    const float* Vb = Kb + 64;
    const int tid  = threadIdx.x;
    const int warp = tid >> 5, lane = tid & 31;
    const int tbase = split * 512 + warp * 128;

    wmma::fragment<wmma::accumulator,16,16,8,float> acc[4][4];
    #pragma unroll
    for (int i = 0; i < 4; i++)
        #pragma unroll
        for (int j = 0; j < 4; j++) wmma::fill_fragment(acc[i][j], 0.f);

    for (int ks = 0; ks < 16; ks++) {
        int t0 = tbase + ks * 8;
        wmma::fragment<wmma::matrix_a,16,16,8,wmma::precision::tf32,wmma::col_major> af[4];
        #pragma unroll
        for (int i = 0; i < 4; i++) {
            wmma::load_matrix_sync(af[i], Kb + (size_t)t0 * 2048 + i*16, 2048);
            #pragma unroll
            for (int e = 0; e < af[i].num_elements; e++)
                af[i].x[e] = wmma::__float_to_tf32(af[i].x[e]);
        }
        #pragma unroll
        for (int j = 0; j < 4; j++) {
            wmma::fragment<wmma::matrix_b,16,16,8,wmma::precision::tf32,wmma::row_major> bf;
            wmma::load_matrix_sync(bf, Vb + (size_t)t0 * 2048 + j*16, 2048);
            #pragma unroll
            for (int e = 0; e < bf.num_elements; e++)
                bf.x[e] = wmma::__float_to_tf32(bf.x[e]);
            #pragma unroll
            for (int i = 0; i < 4; i++)
                wmma::mma_sync(acc[i][j], af[i], bf, acc[i][j]);
        }
    }

    __shared__ float ep[4][320];
    float* buf  = ep[warp];
    float* ctxp = g_ctx + bh * 4096;
    #pragma unroll
    for (int i = 0; i < 4; i++) {
        #pragma unroll
        for (int j = 0; j < 4; j++) {
            __syncwarp();
            wmma::store_matrix_sync(buf, acc[i][j], 20, wmma::mem_row_major);
            __syncwarp();
            for (int t = lane; t < 256; t += 32) {
                int rr = t >> 4, cc = t & 15;
                atomicAdd(&ctxp[(i*16 + rr)*64 + j*16 + cc], buf[rr*20 + cc]);
            }
        }
    }

    int d = tid & 63, grp = tid >> 6;
    float s = 0.f;
    int tstart = split * 512 + grp * 256;
    for (int t = tstart; t < tstart + 256; t++)
        s += Kb[(size_t)t * 2048 + d];
    atomicAdd(&g_ksum[bh * 64 + d], s);
}

// ---------------------------------------------------------------------------
// out[b,t,h,:] = (q @ ctx) * 1/(q·ksum + 1e-6); ksum rides as column 64.
// Output tf32-rounded (feeds GEMM4 as A operand).
// ---------------------------------------------------------------------------
__global__ __launch_bounds__(128)
void attn_out_kernel()
{
    const int bh = blockIdx.x;
    const int tt = blockIdx.y;
    const int b = bh >> 4, h = bh & 15;
    const int tid = threadIdx.x;
    const int warp = tid >> 5, lane = tid & 31;

    __shared__ float Qs[64 * 68];
    __shared__ float Cs[64 * 84];

    const float* Qb = g_Q + (size_t)(b * T_ + tt * 64) * 1024 + h * 64;
    #pragma unroll
    for (int p = 0; p < 8; p++) {
        int idx = tid + p * 128;
        int r = idx >> 4, c4 = (idx & 15) * 4;
        float4 v = *reinterpret_cast<const float4*>(Qb + (size_t)r * 1024 + c4);
        Qs[r*68 + c4    ] = v.x;
        Qs[r*68 + c4 + 1] = v.y;
        Qs[r*68 + c4 + 2] = v.z;
        Qs[r*68 + c4 + 3] = v.w;
    }
    for (int i = tid; i < 64 * 84; i += 128) Cs[i] = 0.f;
    __syncthreads();
    const float* cp = g_ctx + bh * 4096;
    for (int i = tid; i < 4096; i += 128) {
        int d = i >> 6, e = i & 63;
        Cs[d*84 + e] = cp[i];
    }
    if (tid < 64) Cs[tid*84 + 64] = g_ksum[bh * 64 + tid];
    __syncthreads();

    wmma::fragment<wmma::accumulator,16,16,8,float> acc[5];
    #pragma unroll
    for (int j = 0; j < 5; j++) wmma::fill_fragment(acc[j], 0.f);

    #pragma unroll
    for (int k = 0; k < 8; k++) {
        wmma::fragment<wmma::matrix_a,16,16,8,wmma::precision::tf32,wmma::row_major> af;
        wmma::load_matrix_sync(af, &Qs[(warp*16)*68 + k*8], 68);
        #pragma unroll
        for (int e = 0; e < af.num_elements; e++)
            af.x[e] = wmma::__float_to_tf32(af.x[e]);
        #pragma unroll
        for (int j = 0; j < 5; j++) {
            wmma::fragment<wmma::matrix_b,16,16,8,wmma::precision::tf32,wmma::row_major> bf;
            wmma::load_matrix_sync(bf, &Cs[(k*8)*84 + j*16], 84);
            #pragma unroll
            for (int e = 0; e < bf.num_elements; e++)
                bf.x[e] = wmma::__float_to_tf32(bf.x[e]);
            wmma::mma_sync(acc[j], af, bf, acc[j]);
        }
    }
    __syncthreads();

    float* buf = &Cs[(warp*16) * 84];
    #pragma unroll
    for (int j = 0; j < 5; j++)
        wmma::store_matrix_sync(buf + j*16, acc[j], 84, wmma::mem_row_major);
    __syncwarp();

    float* Ob = g_O + (size_t)(b * T_ + tt * 64 + warp * 16) * 1024 + h * 64;
    for (int t = lane; t < 16 * 64; t += 32) {
        int rr = t >> 6, cc = t & 63;
        float z = 1.f / (buf[rr*84 + 64] + 1e-6f);
        Ob[(size_t)rr * 1024 + cc] = wmma::__float_to_tf32(buf[rr*84 + cc] * z);
    }
}

// ---------------------------------------------------------------------------
extern "C" void kernel_launch(void* const* d_in, const int* in_sizes, int n_in,
                              void* d_out, int out_size)
{
    const float* x  = (const float*)d_in[0];
    const float* Wq = (const float*)d_in[1];
    const float* bq = (const float*)d_in[2];
    const float* Wd = (const float*)d_in[3];
    const float* bd = (const float*)d_in[4];
    const float* Wu = (const float*)d_in[5];
    const float* bu = (const float*)d_in[6];
    const float* Wo = (const float*)d_in[7];
    const float* bo = (const float*)d_in[8];
    float* out = (float*)d_out;

    void *pX, *pQ, *pC, *pKV, *pO, *pWq, *pWd, *pWu, *pWo;
    cudaGetSymbolAddress(&pX,  g_X);
    cudaGetSymbolAddress(&pQ,  g_Q);
    cudaGetSymbolAddress(&pC,  g_C);
    cudaGetSymbolAddress(&pKV, g_KV);
    cudaGetSymbolAddress(&pO,  g_O);
    cudaGetSymbolAddress(&pWq, g_WqR);
    cudaGetSymbolAddress(&pWd, g_WdR);
    cudaGetSymbolAddress(&pWu, g_WuR);
    cudaGetSymbolAddress(&pWo, g_WoR);

    const int smem_bytes = SMEM_FLOATS * sizeof(float);   // 70656
    cudaFuncSetAttribute(gemm_tf32<1,1>, cudaFuncAttributeMaxDynamicSharedMemorySize, smem_bytes);
    cudaFuncSetAttribute(gemm_tf32<0,1>, cudaFuncAttributeMaxDynamicSharedMemorySize, smem_bytes);
    cudaFuncSetAttribute(gemm_tf32<2,0>, cudaFuncAttributeMaxDynamicSharedMemorySize, smem_bytes);
    cudaFuncSetAttribute(gemm_tf32<0,0>, cudaFuncAttributeMaxDynamicSharedMemorySize, smem_bytes);

    zero_kernel<<<1024, 256>>>();
    round_copy<<<16384, 256>>>(x,  (float*)pX,  16777216/4);
    round_copy<<<1024,  256>>>(Wq, (float*)pWq, 1048576/4);
    round_copy<<<256,   256>>>(Wd, (float*)pWd, 262144/4);
    round_copy<<<512,   256>>>(Wu, (float*)pWu, 524288/4);
    round_copy<<<1024,  256>>>(Wo, (float*)pWo, 1048576/4);

    // Q = elu(x@Wq + bq) + 1   (rounded: feeds attn_out / GEMM-like use)
    gemm_tf32<1,1><<<dim3(M_/BM, 1024/BN), 256, smem_bytes>>>(
        (const float*)pX, (const float*)pWq, bq, (float*)pQ, 1024, 1024);
    // C = x@Wd + bd            (rounded: feeds GEMM3 as A)
    gemm_tf32<0,1><<<dim3(M_/BM,  256/BN), 256, smem_bytes>>>(
        (const float*)pX, (const float*)pWd, bd, (float*)pC,  256, 1024);
    // KV = C@Wu + bu, elu+1 on k half of each head (fp32: ctx kernel converts)
    gemm_tf32<2,0><<<dim3(M_/BM, 2048/BN), 256, smem_bytes>>>(
        (const float*)pC, (const float*)pWu, bu, (float*)pKV, 2048, 256);

    ctx_kernel<<<dim3(64, 8), 128>>>();
    attn_out_kernel<<<dim3(64, 64), 128>>>();

    // out = O@Wo + bo
    gemm_tf32<0,0><<<dim3(M_/BM, 1024/BN), 256, smem_bytes>>>(
        (const float*)pO, (const float*)pWo, bo, out, 1024, 1024);
}

// round 6
// speedup vs baseline: 4.3700x; 3.1674x over previous
#include <cuda_runtime.h>
#include <cstdint>
#include <cuda_fp16.h>
#include <mma.h>
using namespace nvcuda;

// Problem constants
#define B_  4
#define T_  4096
#define D_  1024
#define H_  16
#define R_  256
#define DH_ 64
#define M_  16384   // B_*T_

// Scratch (allocation-free rule: __device__ globals)
__device__ __half g_Xh [16777216];  // x as fp16
__device__ __half g_Wqh[1048576];
__device__ __half g_Wdh[262144];
__device__ __half g_Wuh[524288];
__device__ __half g_Woh[1048576];
__device__ float  g_Q  [16777216];  // (M,1024) q after elu+1 (fp32, feeds attn)
__device__ __half g_Ch [4194304];   // (M,256)  x@Wd+bd
__device__ __half g_KVh[33554432];  // (M,2048) kv, k-half elu+1'd
__device__ __half g_Oh [16777216];  // (M,1024) attention out * z
__device__ float  g_ctx[262144];    // (B*H,64,64)
__device__ float  g_ksum[4096];     // (B*H,64)

__global__ void zero_kernel() {
    int i = blockIdx.x * blockDim.x + threadIdx.x;
    if (i < 262144) g_ctx[i] = 0.f;
    if (i < 4096)   g_ksum[i] = 0.f;
}

__device__ __forceinline__ void f4_to_h4(const float4 v, __half* dst) {
    __half2 h0 = __floats2half2_rn(v.x, v.y);
    __half2 h1 = __floats2half2_rn(v.z, v.w);
    uint2 u;
    u.x = *reinterpret_cast<unsigned*>(&h0);
    u.y = *reinterpret_cast<unsigned*>(&h1);
    *reinterpret_cast<uint2*>(dst) = u;
}

// x -> half
__global__ void conv_x(const float* __restrict__ x) {
    int i = blockIdx.x * blockDim.x + threadIdx.x;   // float4 idx, 4194304
    float4 v = reinterpret_cast<const float4*>(x)[i];
    f4_to_h4(v, &g_Xh[(size_t)i * 4]);
}

// all 4 weights -> half in one launch (segment by range)
__global__ void conv_w(const float* __restrict__ Wq, const float* __restrict__ Wd,
                       const float* __restrict__ Wu, const float* __restrict__ Wo) {
    int i = blockIdx.x * blockDim.x + threadIdx.x;   // float4 idx, 720896 total
    const float* src; __half* dst; int off;
    if (i < 262144)            { src = Wq; dst = g_Wqh; off = i; }
    else if (i < 327680)       { src = Wd; dst = g_Wdh; off = i - 262144; }
    else if (i < 458752)       { src = Wu; dst = g_Wuh; off = i - 327680; }
    else                       { src = Wo; dst = g_Woh; off = i - 458752; }
    float4 v = reinterpret_cast<const float4*>(src)[off];
    f4_to_h4(v, &dst[(size_t)off * 4]);
}

// ---------------------------------------------------------------------------
// cp.async helpers (16B)
// ---------------------------------------------------------------------------
__device__ __forceinline__ void cp16(void* smem_dst, const void* gmem_src) {
    unsigned s = (unsigned)__cvta_generic_to_shared(smem_dst);
    asm volatile("cp.async.cg.shared.global [%0], [%1], 16;\n" :: "r"(s), "l"(gmem_src));
}
__device__ __forceinline__ void cp_commit() {
    asm volatile("cp.async.commit_group;\n" ::: "memory");
}
template<int N>
__device__ __forceinline__ void cp_wait() {
    asm volatile("cp.async.wait_group %0;\n" :: "n"(N) : "memory");
}

// ---------------------------------------------------------------------------
// fp16 WMMA GEMM (fp32 accumulate), 2-stage cp.async, 2 CTAs/SM.
// C = act(A(MxK) @ B(KxN) + bias)
// ACT: 0 none, 1 elu+1 all cols, 2 elu+1 where (col&127)<64
// OUTH: 1 -> write __half, 0 -> write float
// Tiles: 128x128x64, 8 warps (4x2), warp tile 32x64, wmma 16x16x16
// ---------------------------------------------------------------------------
#define BM 128
#define BN 128
#define BK 64
#define LDAh 72     // 64 + 8 pad (halves); row = 144B, conflict-free LDSM
#define LDBh 136    // 128 + 8 pad
#define STAGE_Ah (BM * LDAh)   // 9216 halves
#define STAGE_Bh (BK * LDBh)   // 8704 halves
#define SMEM_HALVES (2 * (STAGE_Ah + STAGE_Bh))   // 35840 halves = 71680 B

template<int ACT, int OUTH>
__global__ __launch_bounds__(256, 2)
void gemm_f16(const __half* __restrict__ A, const __half* __restrict__ Bm,
              const float* __restrict__ bias, void* __restrict__ Cout,
              int Ndim, int Kdim)
{
    extern __shared__ __half smh[];
    __half* Asm = smh;                      // 2 * STAGE_Ah
    __half* Bsm = smh + 2 * STAGE_Ah;       // 2 * STAGE_Bh

    const int tid  = threadIdx.x;
    const int warp = tid >> 5;
    const int lane = tid & 31;
    const int wm = warp >> 1;               // 0..3
    const int wn = warp & 1;                // 0..1
    const int row0 = blockIdx.x * BM;
    const int col0 = blockIdx.y * BN;
    const int Ktiles = Kdim / BK;

    auto issue = [&](int stage, int kt) {
        __half* as = Asm + stage * STAGE_Ah;
        __half* bs = Bsm + stage * STAGE_Bh;
        const __half* Ag = A + (size_t)row0 * Kdim + (size_t)kt * BK;
        const __half* Bg = Bm + (size_t)kt * BK * Ndim + col0;
        #pragma unroll
        for (int p = 0; p < 4; p++) {       // A: 1024 chunks of 8 halves
            int ci = tid + p * 256;
            int r = ci >> 3, c = (ci & 7) * 8;
            cp16(&as[r * LDAh + c], Ag + (size_t)r * Kdim + c);
        }
        #pragma unroll
        for (int p = 0; p < 4; p++) {       // B: 1024 chunks of 8 halves
            int ci = tid + p * 256;
            int r = ci >> 4, c = (ci & 15) * 8;
            cp16(&bs[r * LDBh + c], Bg + (size_t)r * Ndim + c);
        }
    };

    wmma::fragment<wmma::accumulator,16,16,16,float> acc[2][4];
    #pragma unroll
    for (int i = 0; i < 2; i++)
        #pragma unroll
        for (int j = 0; j < 4; j++) wmma::fill_fragment(acc[i][j], 0.f);

    issue(0, 0); cp_commit();

    for (int kt = 0; kt < Ktiles; kt++) {
        if (kt + 1 < Ktiles) { issue((kt + 1) & 1, kt + 1); cp_commit(); }
        cp_wait<1>();
        __syncthreads();

        const __half* as = Asm + (kt & 1) * STAGE_Ah;
        const __half* bs = Bsm + (kt & 1) * STAGE_Bh;

        #pragma unroll
        for (int kk = 0; kk < 4; kk++) {    // 4 x k=16
            wmma::fragment<wmma::matrix_a,16,16,16,__half,wmma::row_major> af[2];
            #pragma unroll
            for (int i = 0; i < 2; i++)
                wmma::load_matrix_sync(af[i], &as[(wm*32 + i*16)*LDAh + kk*16], LDAh);
            #pragma unroll
            for (int j = 0; j < 4; j++) {
                wmma::fragment<wmma::matrix_b,16,16,16,__half,wmma::row_major> bf;
                wmma::load_matrix_sync(bf, &bs[(kk*16)*LDBh + wn*64 + j*16], LDBh);
                #pragma unroll
                for (int i = 0; i < 2; i++)
                    wmma::mma_sync(acc[i][j], af[i], bf, acc[i][j]);
            }
        }
        __syncthreads();
    }

    // Epilogue: bulk smem staging (reuse pipeline smem as float), float4 path.
    float* ep = reinterpret_cast<float*>(smh) + warp * (32 * 68);  // 69632B < 71680B
    #pragma unroll
    for (int i = 0; i < 2; i++)
        #pragma unroll
        for (int j = 0; j < 4; j++)
            wmma::store_matrix_sync(ep + (i*16)*68 + j*16, acc[i][j], 68,
                                    wmma::mem_row_major);
    __syncwarp();

    const int gr0 = row0 + wm * 32;
    const int gc0 = col0 + wn * 64;
    #pragma unroll
    for (int idx = lane; idx < 512; idx += 32) {   // 32 rows x 16 float4
        int rr = idx >> 4, c4 = (idx & 15) * 4;
        int gc = gc0 + c4;
        float4 v = *reinterpret_cast<const float4*>(&ep[rr*68 + c4]);
        float4 bb = *reinterpret_cast<const float4*>(&bias[gc]);
        v.x += bb.x; v.y += bb.y; v.z += bb.z; v.w += bb.w;
        if (ACT == 1 || (ACT == 2 && (gc & 127) < 64)) {
            v.x = (v.x > 0.f) ? v.x + 1.f : __expf(v.x);
            v.y = (v.y > 0.f) ? v.y + 1.f : __expf(v.y);
            v.z = (v.z > 0.f) ? v.z + 1.f : __expf(v.z);
            v.w = (v.w > 0.f) ? v.w + 1.f : __expf(v.w);
        }
        if (OUTH) {
            f4_to_h4(v, reinterpret_cast<__half*>(Cout) + (size_t)(gr0 + rr) * Ndim + gc);
        } else {
            *reinterpret_cast<float4*>(
                reinterpret_cast<float*>(Cout) + (size_t)(gr0 + rr) * Ndim + gc) = v;
        }
    }
}

// ---------------------------------------------------------------------------
// ctx[b,h] = sum_t k[t,:]^T v[t,:]  (64x64, split-K atomics) + ksum
// fp16 operands, fp32 accumulate. Direct global fragment loads.
// ---------------------------------------------------------------------------
__global__ __launch_bounds__(128)
void ctx_kernel()
{
    const int bh = blockIdx.x;           // 0..63
    const int split = blockIdx.y;        // 0..7
    const int b = bh >> 4, h = bh & 15;
    const __half* Kb = g_KVh + (size_t)b * T_ * 2048 + h * 128;
    const __half* Vb = Kb + 64;
    const int tid  = threadIdx.x;
    const int warp = tid >> 5, lane = tid & 31;
    const int tbase = split * 512 + warp * 128;

    wmma::fragment<wmma::accumulator,16,16,16,float> acc[4][4];
    #pragma unroll
    for (int i = 0; i < 4; i++)
        #pragma unroll
        for (int j = 0; j < 4; j++) wmma::fill_fragment(acc[i][j], 0.f);

    for (int ks = 0; ks < 8; ks++) {     // 8 x k=16 over this warp's 128 tokens
        int t0 = tbase + ks * 16;
        wmma::fragment<wmma::matrix_a,16,16,16,__half,wmma::col_major> af[4];
        #pragma unroll
        for (int i = 0; i < 4; i++)
            wmma::load_matrix_sync(af[i], Kb + (size_t)t0 * 2048 + i*16, 2048);
        #pragma unroll
        for (int j = 0; j < 4; j++) {
            wmma::fragment<wmma::matrix_b,16,16,16,__half,wmma::row_major> bf;
            wmma::load_matrix_sync(bf, Vb + (size_t)t0 * 2048 + j*16, 2048);
            #pragma unroll
            for (int i = 0; i < 4; i++)
                wmma::mma_sync(acc[i][j], af[i], bf, acc[i][j]);
        }
    }

    __shared__ float ep[4][320];
    float* buf  = ep[warp];
    float* ctxp = g_ctx + bh * 4096;
    #pragma unroll
    for (int i = 0; i < 4; i++) {
        #pragma unroll
        for (int j = 0; j < 4; j++) {
            __syncwarp();
            wmma::store_matrix_sync(buf, acc[i][j], 20, wmma::mem_row_major);
            __syncwarp();
            for (int t = lane; t < 256; t += 32) {
                int rr = t >> 4, cc = t & 15;
                atomicAdd(&ctxp[(i*16 + rr)*64 + j*16 + cc], buf[rr*20 + cc]);
            }
        }
    }

    int d = tid & 63, grp = tid >> 6;
    float s = 0.f;
    int tstart = split * 512 + grp * 256;
    for (int t = tstart; t < tstart + 256; t++)
        s += __half2float(Kb[(size_t)t * 2048 + d]);
    atomicAdd(&g_ksum[bh * 64 + d], s);
}

// ---------------------------------------------------------------------------
// out[b,t,h,:] = (q @ ctx) * 1/(q·ksum + 1e-6); ksum rides as column 64.
// Q/ctx fp32 (tf32 WMMA); output written as __half (feeds GEMM4).
// ---------------------------------------------------------------------------
__global__ __launch_bounds__(128)
void attn_out_kernel()
{
    const int bh = blockIdx.x;
    const int tt = blockIdx.y;
    const int b = bh >> 4, h = bh & 15;
    const int tid = threadIdx.x;
    const int warp = tid >> 5, lane = tid & 31;

    __shared__ float Qs[64 * 68];
    __shared__ float Cs[64 * 84];

    const float* Qb = g_Q + (size_t)(b * T_ + tt * 64) * 1024 + h * 64;
    #pragma unroll
    for (int p = 0; p < 8; p++) {
        int idx = tid + p * 128;
        int r = idx >> 4, c4 = (idx & 15) * 4;
        float4 v = *reinterpret_cast<const float4*>(Qb + (size_t)r * 1024 + c4);
        Qs[r*68 + c4    ] = v.x;
        Qs[r*68 + c4 + 1] = v.y;
        Qs[r*68 + c4 + 2] = v.z;
        Qs[r*68 + c4 + 3] = v.w;
    }
    for (int i = tid; i < 64 * 84; i += 128) Cs[i] = 0.f;
    __syncthreads();
    const float* cp = g_ctx + bh * 4096;
    for (int i = tid; i < 4096; i += 128) {
        int d = i >> 6, e = i & 63;
        Cs[d*84 + e] = cp[i];
    }
    if (tid < 64) Cs[tid*84 + 64] = g_ksum[bh * 64 + tid];
    __syncthreads();

    wmma::fragment<wmma::accumulator,16,16,8,float> acc[5];
    #pragma unroll
    for (int j = 0; j < 5; j++) wmma::fill_fragment(acc[j], 0.f);

    #pragma unroll
    for (int k = 0; k < 8; k++) {
        wmma::fragment<wmma::matrix_a,16,16,8,wmma::precision::tf32,wmma::row_major> af;
        wmma::load_matrix_sync(af, &Qs[(warp*16)*68 + k*8], 68);
        #pragma unroll
        for (int e = 0; e < af.num_elements; e++)
            af.x[e] = wmma::__float_to_tf32(af.x[e]);
        #pragma unroll
        for (int j = 0; j < 5; j++) {
            wmma::fragment<wmma::matrix_b,16,16,8,wmma::precision::tf32,wmma::row_major> bf;
            wmma::load_matrix_sync(bf, &Cs[(k*8)*84 + j*16], 84);
            #pragma unroll
            for (int e = 0; e < bf.num_elements; e++)
                bf.x[e] = wmma::__float_to_tf32(bf.x[e]);
            wmma::mma_sync(acc[j], af, bf, acc[j]);
        }
    }
    __syncthreads();

    float* buf = &Cs[(warp*16) * 84];
    #pragma unroll
    for (int j = 0; j < 5; j++)
        wmma::store_matrix_sync(buf + j*16, acc[j], 84, wmma::mem_row_major);
    __syncwarp();

    __half* Ob = g_Oh + (size_t)(b * T_ + tt * 64 + warp * 16) * 1024 + h * 64;
    for (int t = lane; t < 16 * 64; t += 32) {
        int rr = t >> 6, cc = t & 63;
        float z = 1.f / (buf[rr*84 + 64] + 1e-6f);
        Ob[(size_t)rr * 1024 + cc] = __float2half_rn(buf[rr*84 + cc] * z);
    }
}

// ---------------------------------------------------------------------------
extern "C" void kernel_launch(void* const* d_in, const int* in_sizes, int n_in,
                              void* d_out, int out_size)
{
    const float* x  = (const float*)d_in[0];
    const float* Wq = (const float*)d_in[1];
    const float* bq = (const float*)d_in[2];
    const float* Wd = (const float*)d_in[3];
    const float* bd = (const float*)d_in[4];
    const float* Wu = (const float*)d_in[5];
    const float* bu = (const float*)d_in[6];
    const float* Wo = (const float*)d_in[7];
    const float* bo = (const float*)d_in[8];
    float* out = (float*)d_out;

    void *pXh, *pWqh, *pWdh, *pWuh, *pWoh, *pQ, *pCh, *pKVh, *pOh;
    cudaGetSymbolAddress(&pXh,  g_Xh);
    cudaGetSymbolAddress(&pWqh, g_Wqh);
    cudaGetSymbolAddress(&pWdh, g_Wdh);
    cudaGetSymbolAddress(&pWuh, g_Wuh);
    cudaGetSymbolAddress(&pWoh, g_Woh);
    cudaGetSymbolAddress(&pQ,   g_Q);
    cudaGetSymbolAddress(&pCh,  g_Ch);
    cudaGetSymbolAddress(&pKVh, g_KVh);
    cudaGetSymbolAddress(&pOh,  g_Oh);

    const int smem_bytes = SMEM_HALVES * sizeof(__half);   // 71680
    cudaFuncSetAttribute(gemm_f16<1,0>, cudaFuncAttributeMaxDynamicSharedMemorySize, smem_bytes);
    cudaFuncSetAttribute(gemm_f16<0,1>, cudaFuncAttributeMaxDynamicSharedMemorySize, smem_bytes);
    cudaFuncSetAttribute(gemm_f16<2,1>, cudaFuncAttributeMaxDynamicSharedMemorySize, smem_bytes);
    cudaFuncSetAttribute(gemm_f16<0,0>, cudaFuncAttributeMaxDynamicSharedMemorySize, smem_bytes);

    // 3 prep launches so ncu (-s 5) captures gemm3, the largest GEMM
    zero_kernel<<<1024, 256>>>();
    conv_x<<<16384, 256>>>(x);
    conv_w<<<2816, 256>>>(Wq, Wd, Wu, Wo);

    // Q = elu(x@Wq + bq) + 1   (float out; feeds attn)
    gemm_f16<1,0><<<dim3(M_/BM, 1024/BN), 256, smem_bytes>>>(
        (const __half*)pXh, (const __half*)pWqh, bq, pQ, 1024, 1024);
    // C = x@Wd + bd            (half out; feeds gemm3)
    gemm_f16<0,1><<<dim3(M_/BM,  256/BN), 256, smem_bytes>>>(
        (const __half*)pXh, (const __half*)pWdh, bd, pCh,  256, 1024);
    // KV = C@Wu + bu, elu+1 on k half of each head (half out; feeds ctx)
    gemm_f16<2,1><<<dim3(M_/BM, 2048/BN), 256, smem_bytes>>>(
        (const __half*)pCh, (const __half*)pWuh, bu, pKVh, 2048, 256);

    ctx_kernel<<<dim3(64, 8), 128>>>();
    attn_out_kernel<<<dim3(64, 64), 128>>>();

    // out = O@Wo + bo  (float out)
    gemm_f16<0,0><<<dim3(M_/BM, 1024/BN), 256, smem_bytes>>>(
        (const __half*)pOh, (const __half*)pWoh, bo, out, 1024, 1024);
}

// round 8
// speedup vs baseline: 4.6637x; 1.0672x over previous
#include <cuda_runtime.h>
#include <cstdint>
#include <cuda_fp16.h>
#include <mma.h>
using namespace nvcuda;

// Problem constants
#define B_  4
#define T_  4096
#define D_  1024
#define H_  16
#define R_  256
#define DH_ 64
#define M_  16384   // B_*T_

// Scratch (allocation-free rule: __device__ globals)
__device__ __half g_Xh [16777216];  // x as fp16
__device__ __half g_Wfh[1310720];   // fused [Wq|Wd]  (1024 x 1280)
__device__ float  g_bqd[1280];      // fused bias [bq|bd]
__device__ __half g_Wuh[524288];
__device__ __half g_Woh[1048576];
__device__ __half g_Qh [16777216];  // (M,1024) q after elu+1
__device__ __half g_Ch [4194304];   // (M,256)  x@Wd+bd
__device__ __half g_KVh[33554432];  // (M,2048) kv, k-half elu+1'd
__device__ __half g_Oh [16777216];  // (M,1024) attention out * z
__device__ float  g_ctx[262144];    // (B*H,64,64)
__device__ float  g_ksum[4096];     // (B*H,64)

__global__ void zero_kernel() {
    int i = blockIdx.x * blockDim.x + threadIdx.x;
    if (i < 262144) g_ctx[i] = 0.f;
    if (i < 4096)   g_ksum[i] = 0.f;
}

__device__ __forceinline__ void f4_to_h4(const float4 v, __half* dst) {
    __half2 h0 = __floats2half2_rn(v.x, v.y);
    __half2 h1 = __floats2half2_rn(v.z, v.w);
    uint2 u;
    u.x = *reinterpret_cast<unsigned*>(&h0);
    u.y = *reinterpret_cast<unsigned*>(&h1);
    *reinterpret_cast<uint2*>(dst) = u;
}

// x -> half
__global__ void conv_x(const float* __restrict__ x) {
    int i = blockIdx.x * blockDim.x + threadIdx.x;   // float4 idx, 4194304
    float4 v = reinterpret_cast<const float4*>(x)[i];
    f4_to_h4(v, &g_Xh[(size_t)i * 4]);
}

// Build fused [Wq|Wd] + bias, convert Wu/Wo. One launch.
__global__ void conv_w(const float* __restrict__ Wq, const float* __restrict__ Wd,
                       const float* __restrict__ Wu, const float* __restrict__ Wo,
                       const float* __restrict__ bq, const float* __restrict__ bd) {
    int i = blockIdx.x * blockDim.x + threadIdx.x;   // float4 idx
    if (i < 327680) {                                 // fused Wf 1024x1280
        int e = i * 4, r = e / 1280, c = e % 1280;
        float4 v = (c < 1024)
            ? *reinterpret_cast<const float4*>(&Wq[(size_t)r * 1024 + c])
            : *reinterpret_cast<const float4*>(&Wd[(size_t)r * 256 + c - 1024]);
        f4_to_h4(v, &g_Wfh[e]);
    } else if (i < 458752) {                          // Wu
        int j = i - 327680;
        float4 v = reinterpret_cast<const float4*>(Wu)[j];
        f4_to_h4(v, &g_Wuh[(size_t)j * 4]);
    } else if (i < 720896) {                          // Wo
        int j = i - 458752;
        float4 v = reinterpret_cast<const float4*>(Wo)[j];
        f4_to_h4(v, &g_Woh[(size_t)j * 4]);
    } else if (i < 721216) {                          // fused bias (float)
        int e = (i - 720896) * 4;
        float4 v = (e < 1024)
            ? *reinterpret_cast<const float4*>(&bq[e])
            : *reinterpret_cast<const float4*>(&bd[e - 1024]);
        *reinterpret_cast<float4*>(&g_bqd[e]) = v;
    }
}

// ---------------------------------------------------------------------------
// cp.async helpers
// ---------------------------------------------------------------------------
__device__ __forceinline__ void cp16(void* smem_dst, const void* gmem_src) {
    unsigned s = (unsigned)__cvta_generic_to_shared(smem_dst);
    asm volatile("cp.async.cg.shared.global [%0], [%1], 16;\n" :: "r"(s), "l"(gmem_src));
}
__device__ __forceinline__ void cp_commit() {
    asm volatile("cp.async.commit_group;\n" ::: "memory");
}
template<int N>
__device__ __forceinline__ void cp_wait() {
    asm volatile("cp.async.wait_group %0;\n" :: "n"(N) : "memory");
}

// ---------------------------------------------------------------------------
// fp16 WMMA GEMM. CTA tile 128x256x64, warp tile 64x64 (2x4 warps),
// 3-stage cp.async pipeline with ONE syncthreads per k-iter.
// MODE 0: fused QD (cols<1024: elu+1 -> g_Qh; else -> g_Ch)
// MODE 1: KV (elu+1 where (col&127)<64 -> g_KVh)
// MODE 2: plain float out (final)
// ---------------------------------------------------------------------------
#define BM 128
#define BN 256
#define BK 64
#define LDAh 72
#define LDBh 264
#define STAGE_Ah (BM * LDAh)   // 9216 halves
#define STAGE_Bh (BK * LDBh)   // 16896 halves
#define NSTAGE 3
#define GEMM_SMEM (NSTAGE * (STAGE_Ah + STAGE_Bh) * 2)   // 156672 B

template<int MODE>
__global__ __launch_bounds__(256, 1)
void gemm_f16(const __half* __restrict__ A, const __half* __restrict__ Bm,
              const float* __restrict__ bias, float* __restrict__ CoutF,
              int Ndim, int Kdim)
{
    extern __shared__ __half smh[];
    __half* Asm = smh;
    __half* Bsm = smh + NSTAGE * STAGE_Ah;

    const int tid  = threadIdx.x;
    const int warp = tid >> 5;
    const int lane = tid & 31;
    const int wm = warp >> 2;               // 0..1
    const int wn = warp & 3;                // 0..3
    const int row0 = blockIdx.x * BM;
    const int col0 = blockIdx.y * BN;
    const int Ktiles = Kdim / BK;

    auto issue = [&](int stage, int kt) {
        __half* as = Asm + stage * STAGE_Ah;
        __half* bs = Bsm + stage * STAGE_Bh;
        const __half* Ag = A + (size_t)row0 * Kdim + (size_t)kt * BK;
        const __half* Bg = Bm + (size_t)kt * BK * Ndim + col0;
        #pragma unroll
        for (int p = 0; p < 4; p++) {        // A: 1024 chunks of 8 halves
            int ci = tid + p * 256;
            int r = ci >> 3, c = (ci & 7) * 8;
            cp16(&as[r * LDAh + c], Ag + (size_t)r * Kdim + c);
        }
        #pragma unroll
        for (int p = 0; p < 8; p++) {        // B: 2048 chunks of 8 halves
            int ci = tid + p * 256;
            int r = ci >> 5, c = (ci & 31) * 8;
            cp16(&bs[r * LDBh + c], Bg + (size_t)r * Ndim + c);
        }
    };

    wmma::fragment<wmma::accumulator,16,16,16,float> acc[4][4];
    #pragma unroll
    for (int i = 0; i < 4; i++)
        #pragma unroll
        for (int j = 0; j < 4; j++) wmma::fill_fragment(acc[i][j], 0.f);

    issue(0, 0); cp_commit();
    if (Ktiles > 1) { issue(1, 1); cp_commit(); }

    for (int kt = 0; kt < Ktiles; kt++) {
        if (kt + 1 < Ktiles) cp_wait<1>(); else cp_wait<0>();
        __syncthreads();

        const __half* as = Asm + (kt % NSTAGE) * STAGE_Ah;
        const __half* bs = Bsm + (kt % NSTAGE) * STAGE_Bh;

        #pragma unroll
        for (int kk = 0; kk < 4; kk++) {     // 4 x k=16
            wmma::fragment<wmma::matrix_a,16,16,16,__half,wmma::row_major> af[4];
            #pragma unroll
            for (int i = 0; i < 4; i++)
                wmma::load_matrix_sync(af[i], &as[(wm*64 + i*16)*LDAh + kk*16], LDAh);
            #pragma unroll
            for (int j = 0; j < 4; j++) {
                wmma::fragment<wmma::matrix_b,16,16,16,__half,wmma::row_major> bf;
                wmma::load_matrix_sync(bf, &bs[(kk*16)*LDBh + wn*64 + j*16], LDBh);
                #pragma unroll
                for (int i = 0; i < 4; i++)
                    wmma::mma_sync(acc[i][j], af[i], bf, acc[i][j]);
            }
        }

        // issue kt+2 after compute; its stage was last read at iter kt-1,
        // protected by this iter's top syncthreads.
        if (kt + 2 < Ktiles) { issue((kt + 2) % NSTAGE, kt + 2); cp_commit(); }
    }

    __syncthreads();   // all warps done reading pipeline smem

    // Epilogue: 2 passes of 32 rows through per-warp float staging.
    float* ep = reinterpret_cast<float*>(smh) + warp * (32 * 68);   // 69632B total
    #pragma unroll
    for (int pass = 0; pass < 2; pass++) {
        #pragma unroll
        for (int ii = 0; ii < 2; ii++)
            #pragma unroll
            for (int j = 0; j < 4; j++)
                wmma::store_matrix_sync(ep + (ii*16)*68 + j*16,
                                        acc[pass*2 + ii][j], 68, wmma::mem_row_major);
        __syncwarp();

        const int gr0 = row0 + wm * 64 + pass * 32;
        const int gc0 = col0 + wn * 64;
        #pragma unroll
        for (int idx = lane; idx < 512; idx += 32) {   // 32 rows x 16 float4
            int rr = idx >> 4, c4 = (idx & 15) * 4;
            int gc = gc0 + c4;
            float4 v = *reinterpret_cast<const float4*>(&ep[rr*68 + c4]);
            float4 bb = *reinterpret_cast<const float4*>(&bias[gc]);
            v.x += bb.x; v.y += bb.y; v.z += bb.z; v.w += bb.w;
            int gr = gr0 + rr;
            if (MODE == 0) {
                if (gc < 1024) {
                    v.x = (v.x > 0.f) ? v.x + 1.f : __expf(v.x);
                    v.y = (v.y > 0.f) ? v.y + 1.f : __expf(v.y);
                    v.z = (v.z > 0.f) ? v.z + 1.f : __expf(v.z);
                    v.w = (v.w > 0.f) ? v.w + 1.f : __expf(v.w);
                    f4_to_h4(v, &g_Qh[(size_t)gr * 1024 + gc]);
                } else {
                    f4_to_h4(v, &g_Ch[(size_t)gr * 256 + (gc - 1024)]);
                }
            } else if (MODE == 1) {
                if ((gc & 127) < 64) {
                    v.x = (v.x > 0.f) ? v.x + 1.f : __expf(v.x);
                    v.y = (v.y > 0.f) ? v.y + 1.f : __expf(v.y);
                    v.z = (v.z > 0.f) ? v.z + 1.f : __expf(v.z);
                    v.w = (v.w > 0.f) ? v.w + 1.f : __expf(v.w);
                }
                f4_to_h4(v, &g_KVh[(size_t)gr * 2048 + gc]);
            } else {
                *reinterpret_cast<float4*>(&CoutF[(size_t)gr * Ndim + gc]) = v;
            }
        }
        __syncwarp();
    }
}

// ---------------------------------------------------------------------------
// ctx[b,h] = sum_t k[t,:]^T v[t,:] (64x64) + ksum. Smem-staged via cp.async,
// 2-stage, fp16 LDSM fragments. grid (64 bh, 8 splits), block 128 (4 warps).
// Each chunk = 128 tokens x 128 halves (k|v contiguous per token).
// ---------------------------------------------------------------------------
#define CTX_LD 136
#define CTX_STAGE (128 * CTX_LD)                  // halves
#define CTX_SMEM (2 * CTX_STAGE * 2)              // 69632 B dynamic

__global__ __launch_bounds__(128)
void ctx_kernel()
{
    extern __shared__ __half kvs[];
    const int bh = blockIdx.x;           // 0..63
    const int split = blockIdx.y;        // 0..7
    const int b = bh >> 4, h = bh & 15;
    const __half* Kb = g_KVh + (size_t)b * T_ * 2048 + h * 128;  // k|v 128 halves
    const int tid  = threadIdx.x;
    const int warp = tid >> 5, lane = tid & 31;
    const int tbase = split * 512;

    auto issue = [&](int stage, int c) {
        __half* s = kvs + stage * CTX_STAGE;
        const __half* g = Kb + (size_t)(tbase + c * 128) * 2048;
        #pragma unroll
        for (int p = 0; p < 16; p++) {    // 2048 chunks of 8 halves
            int ci = tid + p * 128;
            int r = ci >> 4, cc = (ci & 15) * 8;
            cp16(&s[r * CTX_LD + cc], g + (size_t)r * 2048 + cc);
        }
    };

    wmma::fragment<wmma::accumulator,16,16,16,float> acc[4];
    #pragma unroll
    for (int j = 0; j < 4; j++) wmma::fill_fragment(acc[j], 0.f);
    float ks = 0.f;
    const int kd = tid & 63, kgrp = tid >> 6;   // ksum: 2 groups x 64 tokens

    issue(0, 0); cp_commit();

    for (int c = 0; c < 4; c++) {
        if (c + 1 < 4) { issue((c + 1) & 1, c + 1); cp_commit(); cp_wait<1>(); }
        else cp_wait<0>();
        __syncthreads();

        const __half* s = kvs + (c & 1) * CTX_STAGE;
        #pragma unroll
        for (int k8 = 0; k8 < 8; k8++) {
            int t0 = k8 * 16;
            wmma::fragment<wmma::matrix_a,16,16,16,__half,wmma::col_major> af;
            wmma::load_matrix_sync(af, &s[t0 * CTX_LD + warp * 16], CTX_LD);
            #pragma unroll
            for (int j = 0; j < 4; j++) {
                wmma::fragment<wmma::matrix_b,16,16,16,__half,wmma::row_major> bf;
                wmma::load_matrix_sync(bf, &s[t0 * CTX_LD + 64 + j * 16], CTX_LD);
                wmma::mma_sync(acc[j], af, bf, acc[j]);
            }
        }
        // ksum partial from smem (K cols 0..63)
        #pragma unroll 8
        for (int t = kgrp * 64; t < kgrp * 64 + 64; t++)
            ks += __half2float(s[t * CTX_LD + kd]);
        __syncthreads();
    }

    __shared__ float cep[4][16 * 68];
    float* buf = cep[warp];
    #pragma unroll
    for (int j = 0; j < 4; j++)
        wmma::store_matrix_sync(buf + j * 16, acc[j], 68, wmma::mem_row_major);
    __syncwarp();

    float* ctxp = g_ctx + bh * 4096;
    #pragma unroll
    for (int t = lane; t < 16 * 64; t += 32) {
        int rr = t >> 6, cc = t & 63;
        atomicAdd(&ctxp[(warp * 16 + rr) * 64 + cc], buf[rr * 68 + cc]);
    }
    atomicAdd(&g_ksum[bh * 64 + kd], ks);
}

// ---------------------------------------------------------------------------
// out = (q @ ctx) * 1/(q . ksum + 1e-6).  fp16 WMMA; normalizer in fp32.
// ---------------------------------------------------------------------------
__global__ __launch_bounds__(128)
void attn_out_kernel()
{
    const int bh = blockIdx.x;
    const int tt = blockIdx.y;
    const int b = bh >> 4, h = bh & 15;
    const int tid = threadIdx.x;
    const int warp = tid >> 5, lane = tid & 31;

    __shared__ __half Qsh[64 * 72];
    __shared__ __half Csh[64 * 72];
    __shared__ float  ksf[64];
    __shared__ float  zinv[64];
    __shared__ float  Ep[4][16 * 68];

    const __half* Qb = g_Qh + (size_t)(b * T_ + tt * 64) * 1024 + h * 64;
    #pragma unroll
    for (int p = 0; p < 4; p++) {        // 512 chunks of 8 halves (16B each)
        int idx = tid + p * 128;
        int r = idx >> 3, c = (idx & 7) * 8;
        *reinterpret_cast<uint4*>(&Qsh[r * 72 + c]) =
            *reinterpret_cast<const uint4*>(Qb + (size_t)r * 1024 + c);
    }
    const float* cp = g_ctx + bh * 4096;
    for (int i = tid; i < 4096; i += 128) {
        int d = i >> 6, e = i & 63;
        Csh[d * 72 + e] = __float2half_rn(cp[i]);
    }
    if (tid < 64) ksf[tid] = g_ksum[bh * 64 + tid];
    __syncthreads();

    // fp32 normalizer: zinv[t] = 1/(q[t,:] . ksum + 1e-6)
    if (tid < 64) {
        float s = 0.f;
        #pragma unroll 16
        for (int d = 0; d < 64; d++)
            s += __half2float(Qsh[tid * 72 + d]) * ksf[d];
        zinv[tid] = 1.f / (s + 1e-6f);
    }

    wmma::fragment<wmma::accumulator,16,16,16,float> acc[4];
    #pragma unroll
    for (int j = 0; j < 4; j++) wmma::fill_fragment(acc[j], 0.f);

    #pragma unroll
    for (int k = 0; k < 4; k++) {
        wmma::fragment<wmma::matrix_a,16,16,16,__half,wmma::row_major> af;
        wmma::load_matrix_sync(af, &Qsh[(warp * 16) * 72 + k * 16], 72);
        #pragma unroll
        for (int j = 0; j < 4; j++) {
            wmma::fragment<wmma::matrix_b,16,16,16,__half,wmma::row_major> bf;
            wmma::load_matrix_sync(bf, &Csh[(k * 16) * 72 + j * 16], 72);
            wmma::mma_sync(acc[j], af, bf, acc[j]);
        }
    }
    __syncthreads();   // zinv ready; smem reads done

    float* buf = Ep[warp];
    #pragma unroll
    for (int j = 0; j < 4; j++)
        wmma::store_matrix_sync(buf + j * 16, acc[j], 68, wmma::mem_row_major);
    __syncwarp();

    __half* Ob = g_Oh + (size_t)(b * T_ + tt * 64 + warp * 16) * 1024 + h * 64;
    #pragma unroll
    for (int t = lane; t < 16 * 64; t += 32) {
        int rr = t >> 6, cc = t & 63;
        float z = zinv[warp * 16 + rr];
        Ob[(size_t)rr * 1024 + cc] = __float2half_rn(buf[rr * 68 + cc] * z);
    }
}

// ---------------------------------------------------------------------------
extern "C" void kernel_launch(void* const* d_in, const int* in_sizes, int n_in,
                              void* d_out, int out_size)
{
    const float* x  = (const float*)d_in[0];
    const float* Wq = (const float*)d_in[1];
    const float* bq = (const float*)d_in[2];
    const float* Wd = (const float*)d_in[3];
    const float* bd = (const float*)d_in[4];
    const float* Wu = (const float*)d_in[5];
    const float* bu = (const float*)d_in[6];
    const float* Wo = (const float*)d_in[7];
    const float* bo = (const float*)d_in[8];
    float* out = (float*)d_out;

    void *pXh, *pWfh, *pbqd, *pWuh, *pWoh, *pCh, *pOh;
    cudaGetSymbolAddress(&pXh,  g_Xh);
    cudaGetSymbolAddress(&pWfh, g_Wfh);
    cudaGetSymbolAddress(&pbqd, g_bqd);
    cudaGetSymbolAddress(&pWuh, g_Wuh);
    cudaGetSymbolAddress(&pWoh, g_Woh);
    cudaGetSymbolAddress(&pCh,  g_Ch);
    cudaGetSymbolAddress(&pOh,  g_Oh);

    cudaFuncSetAttribute(gemm_f16<0>, cudaFuncAttributeMaxDynamicSharedMemorySize, GEMM_SMEM);
    cudaFuncSetAttribute(gemm_f16<1>, cudaFuncAttributeMaxDynamicSharedMemorySize, GEMM_SMEM);
    cudaFuncSetAttribute(gemm_f16<2>, cudaFuncAttributeMaxDynamicSharedMemorySize, GEMM_SMEM);
    cudaFuncSetAttribute(ctx_kernel,  cudaFuncAttributeMaxDynamicSharedMemorySize, CTX_SMEM);

    zero_kernel<<<1024, 256>>>();
    conv_x<<<16384, 256>>>(x);
    conv_w<<<2818, 256>>>(Wq, Wd, Wu, Wo, bq, bd);

    // [Q|C] = x @ [Wq|Wd] + [bq|bd], elu+1 on Q half
    gemm_f16<0><<<dim3(M_/BM, 1280/BN), 256, GEMM_SMEM>>>(
        (const __half*)pXh, (const __half*)pWfh, (const float*)pbqd, nullptr, 1280, 1024);
    // KV = C@Wu + bu, elu+1 on k half of each head
    gemm_f16<1><<<dim3(M_/BM, 2048/BN), 256, GEMM_SMEM>>>(
        (const __half*)pCh, (const __half*)pWuh, bu, nullptr, 2048, 256);

    ctx_kernel<<<dim3(64, 8), 128, CTX_SMEM>>>();
    attn_out_kernel<<<dim3(64, 64), 128>>>();

    // out = O@Wo + bo
    gemm_f16<2><<<dim3(M_/BM, 1024/BN), 256, GEMM_SMEM>>>(
        (const __half*)pOh, (const __half*)pWoh, bo, out, 1024, 1024);
}

// round 10
// speedup vs baseline: 5.3759x; 1.1527x over previous
#include <cuda_runtime.h>
#include <cstdint>
#include <cuda_fp16.h>
#include <mma.h>
using namespace nvcuda;

// Problem constants
#define B_  4
#define T_  4096
#define D_  1024
#define H_  16
#define R_  256
#define DH_ 64
#define M_  16384   // B_*T_

// Scratch (allocation-free rule: __device__ globals)
__device__ __half g_Xh [16777216];  // x as fp16
__device__ __half g_Wfh[1310720];   // fused [Wq|Wd]  (1024 x 1280)
__device__ float  g_bqd[1280];      // fused bias [bq|bd]
__device__ __half g_Wuh[524288];
__device__ __half g_Woh[1048576];
__device__ __half g_Qh [16777216];  // (M,1024) q after elu+1
__device__ __half g_Ch [4194304];   // (M,256)  x@Wd+bd
__device__ __half g_KVh[33554432];  // (M,2048) kv, k-half elu+1'd
__device__ __half g_Oh [16777216];  // (M,1024) attention out * z
__device__ float  g_ctx[262144];    // (B*H,64,64)
__device__ float  g_ksum[4096];     // (B*H,64)

__global__ void zero_kernel() {
    int i = blockIdx.x * blockDim.x + threadIdx.x;
    if (i < 262144) g_ctx[i] = 0.f;
    if (i < 4096)   g_ksum[i] = 0.f;
}

__device__ __forceinline__ void f4_to_h4(const float4 v, __half* dst) {
    __half2 h0 = __floats2half2_rn(v.x, v.y);
    __half2 h1 = __floats2half2_rn(v.z, v.w);
    uint2 u;
    u.x = *reinterpret_cast<unsigned*>(&h0);
    u.y = *reinterpret_cast<unsigned*>(&h1);
    *reinterpret_cast<uint2*>(dst) = u;
}

// x -> half
__global__ void conv_x(const float* __restrict__ x) {
    int i = blockIdx.x * blockDim.x + threadIdx.x;   // float4 idx, 4194304
    float4 v = reinterpret_cast<const float4*>(x)[i];
    f4_to_h4(v, &g_Xh[(size_t)i * 4]);
}

// Build fused [Wq|Wd] + bias, convert Wu/Wo. One launch.
__global__ void conv_w(const float* __restrict__ Wq, const float* __restrict__ Wd,
                       const float* __restrict__ Wu, const float* __restrict__ Wo,
                       const float* __restrict__ bq, const float* __restrict__ bd) {
    int i = blockIdx.x * blockDim.x + threadIdx.x;   // float4 idx
    if (i < 327680) {                                 // fused Wf 1024x1280
        int e = i * 4, r = e / 1280, c = e % 1280;
        float4 v = (c < 1024)
            ? *reinterpret_cast<const float4*>(&Wq[(size_t)r * 1024 + c])
            : *reinterpret_cast<const float4*>(&Wd[(size_t)r * 256 + c - 1024]);
        f4_to_h4(v, &g_Wfh[e]);
    } else if (i < 458752) {                          // Wu
        int j = i - 327680;
        float4 v = reinterpret_cast<const float4*>(Wu)[j];
        f4_to_h4(v, &g_Wuh[(size_t)j * 4]);
    } else if (i < 720896) {                          // Wo
        int j = i - 458752;
        float4 v = reinterpret_cast<const float4*>(Wo)[j];
        f4_to_h4(v, &g_Woh[(size_t)j * 4]);
    } else if (i < 721216) {                          // fused bias (float)
        int e = (i - 720896) * 4;
        float4 v = (e < 1024)
            ? *reinterpret_cast<const float4*>(&bq[e])
            : *reinterpret_cast<const float4*>(&bd[e - 1024]);
        *reinterpret_cast<float4*>(&g_bqd[e]) = v;
    }
}

// ---------------------------------------------------------------------------
// cp.async helpers
// ---------------------------------------------------------------------------
__device__ __forceinline__ void cp16(void* smem_dst, const void* gmem_src) {
    unsigned s = (unsigned)__cvta_generic_to_shared(smem_dst);
    asm volatile("cp.async.cg.shared.global [%0], [%1], 16;\n" :: "r"(s), "l"(gmem_src));
}
__device__ __forceinline__ void cp_commit() {
    asm volatile("cp.async.commit_group;\n" ::: "memory");
}
template<int N>
__device__ __forceinline__ void cp_wait() {
    asm volatile("cp.async.wait_group %0;\n" :: "n"(N) : "memory");
}

// ---------------------------------------------------------------------------
// fp16 WMMA GEMM. CTA tile 128x128x64, warp tile 32x64 (4x2 warps),
// 3-stage cp.async pipeline, ONE syncthreads per k-iter, 2 CTAs/SM.
// Safe ordering: wait -> sync -> compute -> issue(kt+2).
//   stage (kt+2)%3 was last READ at iter kt-1; every thread has passed the
//   sync of iter kt (which follows its kt-1 compute), so the write is safe.
// MODE 0: fused QD (cols<1024: elu+1 -> g_Qh; else -> g_Ch)
// MODE 1: KV (elu+1 where (col&127)<64 -> g_KVh)
// MODE 2: plain float out (final)
// ---------------------------------------------------------------------------
#define BM 128
#define BN 128
#define BK 64
#define LDAh 72
#define LDBh 136
#define STAGE_Ah (BM * LDAh)   // 9216 halves
#define STAGE_Bh (BK * LDBh)   // 8704 halves
#define NSTAGE 3
#define GEMM_SMEM (NSTAGE * (STAGE_Ah + STAGE_Bh) * 2)   // 107520 B

template<int MODE>
__global__ __launch_bounds__(256, 2)
void gemm_f16(const __half* __restrict__ A, const __half* __restrict__ Bm,
              const float* __restrict__ bias, float* __restrict__ CoutF,
              int Ndim, int Kdim)
{
    extern __shared__ __half smh[];
    __half* Asm = smh;
    __half* Bsm = smh + NSTAGE * STAGE_Ah;

    const int tid  = threadIdx.x;
    const int warp = tid >> 5;
    const int lane = tid & 31;
    const int wm = warp >> 1;               // 0..3
    const int wn = warp & 1;                // 0..1
    const int row0 = blockIdx.x * BM;
    const int col0 = blockIdx.y * BN;
    const int Ktiles = Kdim / BK;

    auto issue = [&](int stage, int kt) {
        __half* as = Asm + stage * STAGE_Ah;
        __half* bs = Bsm + stage * STAGE_Bh;
        const __half* Ag = A + (size_t)row0 * Kdim + (size_t)kt * BK;
        const __half* Bg = Bm + (size_t)kt * BK * Ndim + col0;
        #pragma unroll
        for (int p = 0; p < 4; p++) {        // A: 1024 chunks of 8 halves
            int ci = tid + p * 256;
            int r = ci >> 3, c = (ci & 7) * 8;
            cp16(&as[r * LDAh + c], Ag + (size_t)r * Kdim + c);
        }
        #pragma unroll
        for (int p = 0; p < 4; p++) {        // B: 1024 chunks of 8 halves
            int ci = tid + p * 256;
            int r = ci >> 4, c = (ci & 15) * 8;
            cp16(&bs[r * LDBh + c], Bg + (size_t)r * Ndim + c);
        }
    };

    wmma::fragment<wmma::accumulator,16,16,16,float> acc[2][4];
    #pragma unroll
    for (int i = 0; i < 2; i++)
        #pragma unroll
        for (int j = 0; j < 4; j++) wmma::fill_fragment(acc[i][j], 0.f);

    issue(0, 0); cp_commit();
    if (Ktiles > 1) { issue(1, 1); cp_commit(); }

    for (int kt = 0; kt < Ktiles; kt++) {
        if (kt + 1 < Ktiles) cp_wait<1>(); else cp_wait<0>();
        __syncthreads();

        const __half* as = Asm + (kt % NSTAGE) * STAGE_Ah;
        const __half* bs = Bsm + (kt % NSTAGE) * STAGE_Bh;

        #pragma unroll
        for (int kk = 0; kk < 4; kk++) {     // 4 x k=16
            wmma::fragment<wmma::matrix_a,16,16,16,__half,wmma::row_major> af[2];
            #pragma unroll
            for (int i = 0; i < 2; i++)
                wmma::load_matrix_sync(af[i], &as[(wm*32 + i*16)*LDAh + kk*16], LDAh);
            #pragma unroll
            for (int j = 0; j < 4; j++) {
                wmma::fragment<wmma::matrix_b,16,16,16,__half,wmma::row_major> bf;
                wmma::load_matrix_sync(bf, &bs[(kk*16)*LDBh + wn*64 + j*16], LDBh);
                #pragma unroll
                for (int i = 0; i < 2; i++)
                    wmma::mma_sync(acc[i][j], af[i], bf, acc[i][j]);
            }
        }

        if (kt + 2 < Ktiles) { issue((kt + 2) % NSTAGE, kt + 2); cp_commit(); }
    }

    __syncthreads();   // all warps done reading pipeline smem

    // Epilogue: per-warp float staging (32x68), then float4 stores.
    float* ep = reinterpret_cast<float*>(smh) + warp * (32 * 68);   // 69632B total
    #pragma unroll
    for (int ii = 0; ii < 2; ii++)
        #pragma unroll
        for (int j = 0; j < 4; j++)
            wmma::store_matrix_sync(ep + (ii*16)*68 + j*16, acc[ii][j], 68,
                                    wmma::mem_row_major);
    __syncwarp();

    const int gr0 = row0 + wm * 32;
    const int gc0 = col0 + wn * 64;
    #pragma unroll
    for (int idx = lane; idx < 512; idx += 32) {   // 32 rows x 16 float4
        int rr = idx >> 4, c4 = (idx & 15) * 4;
        int gc = gc0 + c4;
        float4 v = *reinterpret_cast<const float4*>(&ep[rr*68 + c4]);
        float4 bb = *reinterpret_cast<const float4*>(&bias[gc]);
        v.x += bb.x; v.y += bb.y; v.z += bb.z; v.w += bb.w;
        int gr = gr0 + rr;
        if (MODE == 0) {
            if (gc < 1024) {
                v.x = (v.x > 0.f) ? v.x + 1.f : __expf(v.x);
                v.y = (v.y > 0.f) ? v.y + 1.f : __expf(v.y);
                v.z = (v.z > 0.f) ? v.z + 1.f : __expf(v.z);
                v.w = (v.w > 0.f) ? v.w + 1.f : __expf(v.w);
                f4_to_h4(v, &g_Qh[(size_t)gr * 1024 + gc]);
            } else {
                f4_to_h4(v, &g_Ch[(size_t)gr * 256 + (gc - 1024)]);
            }
        } else if (MODE == 1) {
            if ((gc & 127) < 64) {
                v.x = (v.x > 0.f) ? v.x + 1.f : __expf(v.x);
                v.y = (v.y > 0.f) ? v.y + 1.f : __expf(v.y);
                v.z = (v.z > 0.f) ? v.z + 1.f : __expf(v.z);
                v.w = (v.w > 0.f) ? v.w + 1.f : __expf(v.w);
            }
            f4_to_h4(v, &g_KVh[(size_t)gr * 2048 + gc]);
        } else {
            *reinterpret_cast<float4*>(&CoutF[(size_t)gr * Ndim + gc]) = v;
        }
    }
}

// ---------------------------------------------------------------------------
// ctx[b,h] = sum_t k[t,:]^T v[t,:] (64x64) + ksum. Smem-staged via cp.async,
// 2-stage, fp16 LDSM fragments. grid (64 bh, 8 splits), block 128 (4 warps).
// ---------------------------------------------------------------------------
#define CTX_LD 136
#define CTX_STAGE (128 * CTX_LD)                  // halves
#define CTX_SMEM (2 * CTX_STAGE * 2)              // 69632 B dynamic

__global__ __launch_bounds__(128)
void ctx_kernel()
{
    extern __shared__ __half kvs[];
    const int bh = blockIdx.x;           // 0..63
    const int split = blockIdx.y;        // 0..7
    const int b = bh >> 4, h = bh & 15;
    const __half* Kb = g_KVh + (size_t)b * T_ * 2048 + h * 128;  // k|v 128 halves
    const int tid  = threadIdx.x;
    const int warp = tid >> 5, lane = tid & 31;
    const int tbase = split * 512;

    auto issue = [&](int stage, int c) {
        __half* s = kvs + stage * CTX_STAGE;
        const __half* g = Kb + (size_t)(tbase + c * 128) * 2048;
        #pragma unroll
        for (int p = 0; p < 16; p++) {    // 2048 chunks of 8 halves
            int ci = tid + p * 128;
            int r = ci >> 4, cc = (ci & 15) * 8;
            cp16(&s[r * CTX_LD + cc], g + (size_t)r * 2048 + cc);
        }
    };

    wmma::fragment<wmma::accumulator,16,16,16,float> acc[4];
    #pragma unroll
    for (int j = 0; j < 4; j++) wmma::fill_fragment(acc[j], 0.f);
    float ks = 0.f;
    const int kd = tid & 63, kgrp = tid >> 6;   // ksum: 2 groups x 64 tokens

    issue(0, 0); cp_commit();

    for (int c = 0; c < 4; c++) {
        if (c + 1 < 4) { issue((c + 1) & 1, c + 1); cp_commit(); cp_wait<1>(); }
        else cp_wait<0>();
        __syncthreads();

        const __half* s = kvs + (c & 1) * CTX_STAGE;
        #pragma unroll
        for (int k8 = 0; k8 < 8; k8++) {
            int t0 = k8 * 16;
            wmma::fragment<wmma::matrix_a,16,16,16,__half,wmma::col_major> af;
            wmma::load_matrix_sync(af, &s[t0 * CTX_LD + warp * 16], CTX_LD);
            #pragma unroll
            for (int j = 0; j < 4; j++) {
                wmma::fragment<wmma::matrix_b,16,16,16,__half,wmma::row_major> bf;
                wmma::load_matrix_sync(bf, &s[t0 * CTX_LD + 64 + j * 16], CTX_LD);
                wmma::mma_sync(acc[j], af, bf, acc[j]);
            }
        }
        // ksum partial from smem (K cols 0..63)
        #pragma unroll 8
        for (int t = kgrp * 64; t < kgrp * 64 + 64; t++)
            ks += __half2float(s[t * CTX_LD + kd]);
        __syncthreads();
    }

    __shared__ float cep[4][16 * 68];
    float* buf = cep[warp];
    #pragma unroll
    for (int j = 0; j < 4; j++)
        wmma::store_matrix_sync(buf + j * 16, acc[j], 68, wmma::mem_row_major);
    __syncwarp();

    float* ctxp = g_ctx + bh * 4096;
    #pragma unroll
    for (int t = lane; t < 16 * 64; t += 32) {
        int rr = t >> 6, cc = t & 63;
        atomicAdd(&ctxp[(warp * 16 + rr) * 64 + cc], buf[rr * 68 + cc]);
    }
    atomicAdd(&g_ksum[bh * 64 + kd], ks);
}

// ---------------------------------------------------------------------------
// out = (q @ ctx) * 1/(q . ksum + 1e-6).  fp16 WMMA; normalizer in fp32.
// ---------------------------------------------------------------------------
__global__ __launch_bounds__(128)
void attn_out_kernel()
{
    const int bh = blockIdx.x;
    const int tt = blockIdx.y;
    const int b = bh >> 4, h = bh & 15;
    const int tid = threadIdx.x;
    const int warp = tid >> 5, lane = tid & 31;

    __shared__ __half Qsh[64 * 72];
    __shared__ __half Csh[64 * 72];
    __shared__ float  ksf[64];
    __shared__ float  zinv[64];
    __shared__ float  Ep[4][16 * 68];

    const __half* Qb = g_Qh + (size_t)(b * T_ + tt * 64) * 1024 + h * 64;
    #pragma unroll
    for (int p = 0; p < 4; p++) {        // 512 chunks of 8 halves (16B each)
        int idx = tid + p * 128;
        int r = idx >> 3, c = (idx & 7) * 8;
        *reinterpret_cast<uint4*>(&Qsh[r * 72 + c]) =
            *reinterpret_cast<const uint4*>(Qb + (size_t)r * 1024 + c);
    }
    const float* cp = g_ctx + bh * 4096;
    for (int i = tid; i < 4096; i += 128) {
        int d = i >> 6, e = i & 63;
        Csh[d * 72 + e] = __float2half_rn(cp[i]);
    }
    if (tid < 64) ksf[tid] = g_ksum[bh * 64 + tid];
    __syncthreads();

    // fp32 normalizer: zinv[t] = 1/(q[t,:] . ksum + 1e-6)
    if (tid < 64) {
        float s = 0.f;
        #pragma unroll 16
        for (int d = 0; d < 64; d++)
            s += __half2float(Qsh[tid * 72 + d]) * ksf[d];
        zinv[tid] = 1.f / (s + 1e-6f);
    }

    wmma::fragment<wmma::accumulator,16,16,16,float> acc[4];
    #pragma unroll
    for (int j = 0; j < 4; j++) wmma::fill_fragment(acc[j], 0.f);

    #pragma unroll
    for (int k = 0; k < 4; k++) {
        wmma::fragment<wmma::matrix_a,16,16,16,__half,wmma::row_major> af;
        wmma::load_matrix_sync(af, &Qsh[(warp * 16) * 72 + k * 16], 72);
        #pragma unroll
        for (int j = 0; j < 4; j++) {
            wmma::fragment<wmma::matrix_b,16,16,16,__half,wmma::row_major> bf;
            wmma::load_matrix_sync(bf, &Csh[(k * 16) * 72 + j * 16], 72);
            wmma::mma_sync(acc[j], af, bf, acc[j]);
        }
    }
    __syncthreads();   // zinv ready; smem reads done

    float* buf = Ep[warp];
    #pragma unroll
    for (int j = 0; j < 4; j++)
        wmma::store_matrix_sync(buf + j * 16, acc[j], 68, wmma::mem_row_major);
    __syncwarp();

    __half* Ob = g_Oh + (size_t)(b * T_ + tt * 64 + warp * 16) * 1024 + h * 64;
    #pragma unroll
    for (int t = lane; t < 16 * 64; t += 32) {
        int rr = t >> 6, cc = t & 63;
        float z = zinv[warp * 16 + rr];
        Ob[(size_t)rr * 1024 + cc] = __float2half_rn(buf[rr * 68 + cc] * z);
    }
}

// ---------------------------------------------------------------------------
extern "C" void kernel_launch(void* const* d_in, const int* in_sizes, int n_in,
                              void* d_out, int out_size)
{
    const float* x  = (const float*)d_in[0];
    const float* Wq = (const float*)d_in[1];
    const float* bq = (const float*)d_in[2];
    const float* Wd = (const float*)d_in[3];
    const float* bd = (const float*)d_in[4];
    const float* Wu = (const float*)d_in[5];
    const float* bu = (const float*)d_in[6];
    const float* Wo = (const float*)d_in[7];
    const float* bo = (const float*)d_in[8];
    float* out = (float*)d_out;

    void *pXh, *pWfh, *pbqd, *pWuh, *pWoh, *pCh, *pOh;
    cudaGetSymbolAddress(&pXh,  g_Xh);
    cudaGetSymbolAddress(&pWfh, g_Wfh);
    cudaGetSymbolAddress(&pbqd, g_bqd);
    cudaGetSymbolAddress(&pWuh, g_Wuh);
    cudaGetSymbolAddress(&pWoh, g_Woh);
    cudaGetSymbolAddress(&pCh,  g_Ch);
    cudaGetSymbolAddress(&pOh,  g_Oh);

    cudaFuncSetAttribute(gemm_f16<0>, cudaFuncAttributeMaxDynamicSharedMemorySize, GEMM_SMEM);
    cudaFuncSetAttribute(gemm_f16<1>, cudaFuncAttributeMaxDynamicSharedMemorySize, GEMM_SMEM);
    cudaFuncSetAttribute(gemm_f16<2>, cudaFuncAttributeMaxDynamicSharedMemorySize, GEMM_SMEM);
    cudaFuncSetAttribute(ctx_kernel,  cudaFuncAttributeMaxDynamicSharedMemorySize, CTX_SMEM);

    zero_kernel<<<1024, 256>>>();
    conv_x<<<16384, 256>>>(x);
    conv_w<<<2818, 256>>>(Wq, Wd, Wu, Wo, bq, bd);

    // [Q|C] = x @ [Wq|Wd] + [bq|bd], elu+1 on Q half
    gemm_f16<0><<<dim3(M_/BM, 1280/BN), 256, GEMM_SMEM>>>(
        (const __half*)pXh, (const __half*)pWfh, (const float*)pbqd, nullptr, 1280, 1024);
    // KV = C@Wu + bu, elu+1 on k half of each head
    gemm_f16<1><<<dim3(M_/BM, 2048/BN), 256, GEMM_SMEM>>>(
        (const __half*)pCh, (const __half*)pWuh, bu, nullptr, 2048, 256);

    ctx_kernel<<<dim3(64, 8), 128, CTX_SMEM>>>();
    attn_out_kernel<<<dim3(64, 64), 128>>>();

    // out = O@Wo + bo
    gemm_f16<2><<<dim3(M_/BM, 1024/BN), 256, GEMM_SMEM>>>(
        (const __half*)pOh, (const __half*)pWoh, bo, out, 1024, 1024);
}

// round 13
// speedup vs baseline: 5.6166x; 1.0448x over previous
#include <cuda_runtime.h>
#include <cstdint>
#include <cuda_fp16.h>
#include <mma.h>
using namespace nvcuda;

// Problem constants
#define B_  4
#define T_  4096
#define D_  1024
#define H_  16
#define R_  256
#define DH_ 64
#define M_  16384   // B_*T_

// Scratch (allocation-free rule: __device__ globals)
__device__ __half g_Xh [16777216];  // x as fp16
__device__ __half g_Wfh[1310720];   // fused [Wq|Wd]  (1024 x 1280)
__device__ float  g_bqd[1280];      // fused bias [bq|bd]
__device__ __half g_Wuh[524288];
__device__ __half g_Woh[1048576];
__device__ __half g_Qh [16777216];  // (M,1024) q after elu+1
__device__ __half g_Ch [4194304];   // (M,256)  x@Wd+bd
__device__ __half g_KVh[33554432];  // (M,2048) kv, k-half elu+1'd
__device__ __half g_Oh [16777216];  // (M,1024) attention out * z
__device__ float  g_ctx[262144];    // (B*H,64,64)
__device__ float  g_ksum[4096];     // (B*H,64)

__device__ __forceinline__ void f4_to_h4(const float4 v, __half* dst) {
    __half2 h0 = __floats2half2_rn(v.x, v.y);
    __half2 h1 = __floats2half2_rn(v.z, v.w);
    uint2 u;
    u.x = *reinterpret_cast<unsigned*>(&h0);
    u.y = *reinterpret_cast<unsigned*>(&h1);
    *reinterpret_cast<uint2*>(dst) = u;
}

// ---------------------------------------------------------------------------
// Fused prep: zero ctx/ksum, x->fp16, build [Wq|Wd] fp16 + fused bias,
// convert Wu/Wo. Segments in float4 units.
// ---------------------------------------------------------------------------
#define P_X    4194304
#define P_WF   (P_X + 327680)       // 4521984
#define P_WU   (P_WF + 131072)      // 4653056
#define P_WO   (P_WU + 262144)      // 4915200
#define P_BIAS (P_WO + 320)         // 4915520
#define P_CTX  (P_BIAS + 65536)     // 4981056
#define P_KS   (P_CTX + 1024)       // 4982080
#define PREP_BLOCKS ((P_KS + 255) / 256)

__global__ void prep_kernel(const float* __restrict__ x,
                            const float* __restrict__ Wq, const float* __restrict__ Wd,
                            const float* __restrict__ Wu, const float* __restrict__ Wo,
                            const float* __restrict__ bq, const float* __restrict__ bd) {
    int i = blockIdx.x * blockDim.x + threadIdx.x;
    if (i < P_X) {
        float4 v = reinterpret_cast<const float4*>(x)[i];
        f4_to_h4(v, &g_Xh[(size_t)i * 4]);
    } else if (i < P_WF) {
        int e = (i - P_X) * 4, r = e / 1280, c = e % 1280;
        float4 v = (c < 1024)
            ? *reinterpret_cast<const float4*>(&Wq[(size_t)r * 1024 + c])
            : *reinterpret_cast<const float4*>(&Wd[(size_t)r * 256 + c - 1024]);
        f4_to_h4(v, &g_Wfh[e]);
    } else if (i < P_WU) {
        int j = i - P_WF;
        float4 v = reinterpret_cast<const float4*>(Wu)[j];
        f4_to_h4(v, &g_Wuh[(size_t)j * 4]);
    } else if (i < P_WO) {
        int j = i - P_WU;
        float4 v = reinterpret_cast<const float4*>(Wo)[j];
        f4_to_h4(v, &g_Woh[(size_t)j * 4]);
    } else if (i < P_BIAS) {
        int e = (i - P_WO) * 4;
        float4 v = (e < 1024)
            ? *reinterpret_cast<const float4*>(&bq[e])
            : *reinterpret_cast<const float4*>(&bd[e - 1024]);
        *reinterpret_cast<float4*>(&g_bqd[e]) = v;
    } else if (i < P_CTX) {
        int j = i - P_BIAS;
        reinterpret_cast<float4*>(g_ctx)[j] = make_float4(0.f, 0.f, 0.f, 0.f);
    } else if (i < P_KS) {
        int j = i - P_CTX;
        reinterpret_cast<float4*>(g_ksum)[j] = make_float4(0.f, 0.f, 0.f, 0.f);
    }
}

// ---------------------------------------------------------------------------
// cp.async helpers
// ---------------------------------------------------------------------------
__device__ __forceinline__ void cp16(void* smem_dst, const void* gmem_src) {
    unsigned s = (unsigned)__cvta_generic_to_shared(smem_dst);
    asm volatile("cp.async.cg.shared.global [%0], [%1], 16;\n" :: "r"(s), "l"(gmem_src));
}
__device__ __forceinline__ void cp_commit() {
    asm volatile("cp.async.commit_group;\n" ::: "memory");
}
template<int N>
__device__ __forceinline__ void cp_wait() {
    asm volatile("cp.async.wait_group %0;\n" :: "n"(N) : "memory");
}

// ---------------------------------------------------------------------------
// fp16 WMMA GEMM. CTA tile 128x128x64, warp tile 32x64 (4x2 warps),
// 3-stage cp.async pipeline, ONE syncthreads per k-iter, 2 CTAs/SM.
// Grid: (N/BN, M/BM) — x = column tile (fastest) so a wave covers all column
// tiles and B stays L2-resident while A tiles are reused across columns.
// MODE 0: fused QD (cols<1024: elu+1 -> g_Qh; else -> g_Ch)
// MODE 1: KV (elu+1 where (col&127)<64 -> g_KVh)
// MODE 2: plain float out (final)
// ---------------------------------------------------------------------------
#define BM 128
#define BN 128
#define BK 64
#define LDAh 72
#define LDBh 136
#define STAGE_Ah (BM * LDAh)   // 9216 halves
#define STAGE_Bh (BK * LDBh)   // 8704 halves
#define NSTAGE 3
#define GEMM_SMEM (NSTAGE * (STAGE_Ah + STAGE_Bh) * 2)   // 107520 B

template<int MODE>
__global__ __launch_bounds__(256, 2)
void gemm_f16(const __half* __restrict__ A, const __half* __restrict__ Bm,
              const float* __restrict__ bias, float* __restrict__ CoutF,
              int Ndim, int Kdim)
{
    extern __shared__ __half smh[];
    __half* Asm = smh;
    __half* Bsm = smh + NSTAGE * STAGE_Ah;

    const int tid  = threadIdx.x;
    const int warp = tid >> 5;
    const int lane = tid & 31;
    const int wm = warp >> 1;               // 0..3
    const int wn = warp & 1;                // 0..1
    const int row0 = blockIdx.y * BM;
    const int col0 = blockIdx.x * BN;
    const int Ktiles = Kdim / BK;

    // Hoisted per-thread staging offsets (constant across the k-loop).
    const unsigned a_soff = (unsigned)(tid >> 3) * LDAh + (tid & 7) * 8;
    const size_t   a_goff = (size_t)(tid >> 3) * Kdim + (tid & 7) * 8;
    const unsigned b_soff = (unsigned)(tid >> 4) * LDBh + (tid & 15) * 8;
    const size_t   b_goff = (size_t)(tid >> 4) * Ndim + (tid & 15) * 8;
    const __half* Abase = A + (size_t)row0 * Kdim + a_goff;
    const __half* Bbase = Bm + col0 + b_goff;

    auto issue = [&](int stage, int kt) {
        __half* as = Asm + stage * STAGE_Ah + a_soff;
        __half* bs = Bsm + stage * STAGE_Bh + b_soff;
        const __half* Ag = Abase + (size_t)kt * BK;
        const __half* Bg = Bbase + (size_t)kt * BK * Ndim;
        #pragma unroll
        for (int p = 0; p < 4; p++)          // A: 128 rows, 32/step
            cp16(as + p * 32 * LDAh, Ag + (size_t)p * 32 * Kdim);
        #pragma unroll
        for (int p = 0; p < 4; p++)          // B: 64 rows, 16/step
            cp16(bs + p * 16 * LDBh, Bg + (size_t)p * 16 * Ndim);
        cp_commit();
    };

    wmma::fragment<wmma::accumulator,16,16,16,float> acc[2][4];
    #pragma unroll
    for (int i = 0; i < 2; i++)
        #pragma unroll
        for (int j = 0; j < 4; j++) wmma::fill_fragment(acc[i][j], 0.f);

    issue(0, 0);
    if (Ktiles > 1) issue(1, 1);

    for (int kt = 0; kt < Ktiles; kt++) {
        if (kt + 1 < Ktiles) cp_wait<1>(); else cp_wait<0>();
        __syncthreads();

        const __half* as = Asm + (kt % NSTAGE) * STAGE_Ah;
        const __half* bs = Bsm + (kt % NSTAGE) * STAGE_Bh;

        #pragma unroll
        for (int kk = 0; kk < 4; kk++) {     // 4 x k=16
            wmma::fragment<wmma::matrix_a,16,16,16,__half,wmma::row_major> af[2];
            #pragma unroll
            for (int i = 0; i < 2; i++)
                wmma::load_matrix_sync(af[i], &as[(wm*32 + i*16)*LDAh + kk*16], LDAh);
            #pragma unroll
            for (int j = 0; j < 4; j++) {
                wmma::fragment<wmma::matrix_b,16,16,16,__half,wmma::row_major> bf;
                wmma::load_matrix_sync(bf, &bs[(kk*16)*LDBh + wn*64 + j*16], LDBh);
                #pragma unroll
                for (int i = 0; i < 2; i++)
                    wmma::mma_sync(acc[i][j], af[i], bf, acc[i][j]);
            }
        }

        if (kt + 2 < Ktiles) issue((kt + 2) % NSTAGE, kt + 2);
    }

    __syncthreads();   // all warps done reading pipeline smem

    // Epilogue: per-warp float staging (32x68), then float4 stores.
    float* ep = reinterpret_cast<float*>(smh) + warp * (32 * 68);   // 69632B total
    #pragma unroll
    for (int ii = 0; ii < 2; ii++)
        #pragma unroll
        for (int j = 0; j < 4; j++)
            wmma::store_matrix_sync(ep + (ii*16)*68 + j*16, acc[ii][j], 68,
                                    wmma::mem_row_major);
    __syncwarp();

    const int gr0 = row0 + wm * 32;
    const int gc0 = col0 + wn * 64;
    #pragma unroll
    for (int idx = lane; idx < 512; idx += 32) {   // 32 rows x 16 float4
        int rr = idx >> 4, c4 = (idx & 15) * 4;
        int gc = gc0 + c4;
        float4 v = *reinterpret_cast<const float4*>(&ep[rr*68 + c4]);
        float4 bb = *reinterpret_cast<const float4*>(&bias[gc]);
        v.x += bb.x; v.y += bb.y; v.z += bb.z; v.w += bb.w;
        int gr = gr0 + rr;
        if (MODE == 0) {
            if (gc < 1024) {
                v.x = (v.x > 0.f) ? v.x + 1.f : __expf(v.x);
                v.y = (v.y > 0.f) ? v.y + 1.f : __expf(v.y);
                v.z = (v.z > 0.f) ? v.z + 1.f : __expf(v.z);
                v.w = (v.w > 0.f) ? v.w + 1.f : __expf(v.w);
                f4_to_h4(v, &g_Qh[(size_t)gr * 1024 + gc]);
            } else {
                f4_to_h4(v, &g_Ch[(size_t)gr * 256 + (gc - 1024)]);
            }
        } else if (MODE == 1) {
            if ((gc & 127) < 64) {
                v.x = (v.x > 0.f) ? v.x + 1.f : __expf(v.x);
                v.y = (v.y > 0.f) ? v.y + 1.f : __expf(v.y);
                v.z = (v.z > 0.f) ? v.z + 1.f : __expf(v.z);
                v.w = (v.w > 0.f) ? v.w + 1.f : __expf(v.w);
            }
            f4_to_h4(v, &g_KVh[(size_t)gr * 2048 + gc]);
        } else {
            *reinterpret_cast<float4*>(&CoutF[(size_t)gr * Ndim + gc]) = v;
        }
    }
}

// ---------------------------------------------------------------------------
// ctx[b,h] = sum_t k[t,:]^T v[t,:] (64x64) + ksum. Smem-staged via cp.async,
// 2-stage, fp16 LDSM fragments. grid (64 bh, 8 splits), block 128 (4 warps).
// ---------------------------------------------------------------------------
#define CTX_LD 136
#define CTX_STAGE (128 * CTX_LD)                  // halves
#define CTX_SMEM (2 * CTX_STAGE * 2)              // 69632 B dynamic

__global__ __launch_bounds__(128)
void ctx_kernel()
{
    extern __shared__ __half kvs[];
    const int bh = blockIdx.x;           // 0..63
    const int split = blockIdx.y;        // 0..7
    const int b = bh >> 4, h = bh & 15;
    const __half* Kb = g_KVh + (size_t)b * T_ * 2048 + h * 128;  // k|v 128 halves
    const int tid  = threadIdx.x;
    const int warp = tid >> 5, lane = tid & 31;
    const int tbase = split * 512;

    auto issue = [&](int stage, int c) {
        __half* s = kvs + stage * CTX_STAGE;
        const __half* g = Kb + (size_t)(tbase + c * 128) * 2048;
        #pragma unroll
        for (int p = 0; p < 16; p++) {    // 2048 chunks of 8 halves
            int ci = tid + p * 128;
            int r = ci >> 4, cc = (ci & 15) * 8;
            cp16(&s[r * CTX_LD + cc], g + (size_t)r * 2048 + cc);
        }
    };

    wmma::fragment<wmma::accumulator,16,16,16,float> acc[4];
    #pragma unroll
    for (int j = 0; j < 4; j++) wmma::fill_fragment(acc[j], 0.f);
    float ks = 0.f;
    const int kd = tid & 63, kgrp = tid >> 6;   // ksum: 2 groups x 64 tokens

    issue(0, 0); cp_commit();

    for (int c = 0; c < 4; c++) {
        if (c + 1 < 4) { issue((c + 1) & 1, c + 1); cp_commit(); cp_wait<1>(); }
        else cp_wait<0>();
        __syncthreads();

        const __half* s = kvs + (c & 1) * CTX_STAGE;
        #pragma unroll
        for (int k8 = 0; k8 < 8; k8++) {
            int t0 = k8 * 16;
            wmma::fragment<wmma::matrix_a,16,16,16,__half,wmma::col_major> af;
            wmma::load_matrix_sync(af, &s[t0 * CTX_LD + warp * 16], CTX_LD);
            #pragma unroll
            for (int j = 0; j < 4; j++) {
                wmma::fragment<wmma::matrix_b,16,16,16,__half,wmma::row_major> bf;
                wmma::load_matrix_sync(bf, &s[t0 * CTX_LD + 64 + j * 16], CTX_LD);
                wmma::mma_sync(acc[j], af, bf, acc[j]);
            }
        }
        // ksum partial from smem (K cols 0..63)
        #pragma unroll 8
        for (int t = kgrp * 64; t < kgrp * 64 + 64; t++)
            ks += __half2float(s[t * CTX_LD + kd]);
        __syncthreads();
    }

    __shared__ float cep[4][16 * 68];
    float* buf = cep[warp];
    #pragma unroll
    for (int j = 0; j < 4; j++)
        wmma::store_matrix_sync(buf + j * 16, acc[j], 68, wmma::mem_row_major);
    __syncwarp();

    float* ctxp = g_ctx + bh * 4096;
    #pragma unroll
    for (int t = lane; t < 16 * 64; t += 32) {
        int rr = t >> 6, cc = t & 63;
        atomicAdd(&ctxp[(warp * 16 + rr) * 64 + cc], buf[rr * 68 + cc]);
    }
    atomicAdd(&g_ksum[bh * 64 + kd], ks);
}

// ---------------------------------------------------------------------------
// out = (q @ ctx) * 1/(q . ksum + 1e-6).  fp16 WMMA; normalizer in fp32.
// Block handles 256 tokens (4 tiles of 64) for one (b,h): ctx loaded once.
// grid (64 bh, 16 groups), block 128.
// ---------------------------------------------------------------------------
__global__ __launch_bounds__(128)
void attn_out_kernel()
{
    const int bh = blockIdx.x;
    const int grp = blockIdx.y;          // 0..15, each 256 tokens
    const int b = bh >> 4, h = bh & 15;
    const int tid = threadIdx.x;
    const int warp = tid >> 5, lane = tid & 31;

    __shared__ __half Qsh[64 * 72];
    __shared__ __half Csh[64 * 72];
    __shared__ float  ksf[64];
    __shared__ float  zinv[64];
    __shared__ float  Ep[4][16 * 68];

    // Load ctx + ksum once per block.
    const float* cp = g_ctx + bh * 4096;
    for (int i = tid; i < 4096; i += 128) {
        int d = i >> 6, e = i & 63;
        Csh[d * 72 + e] = __float2half_rn(cp[i]);
    }
    if (tid < 64) ksf[tid] = g_ksum[bh * 64 + tid];

    for (int sub = 0; sub < 4; sub++) {
        int tt = grp * 4 + sub;          // 64-token tile index
        __syncthreads();                 // prior iter's zinv/Qsh reads done

        const __half* Qb = g_Qh + (size_t)(b * T_ + tt * 64) * 1024 + h * 64;
        #pragma unroll
        for (int p = 0; p < 4; p++) {    // 512 chunks of 8 halves (16B each)
            int idx = tid + p * 128;
            int r = idx >> 3, c = (idx & 7) * 8;
            *reinterpret_cast<uint4*>(&Qsh[r * 72 + c]) =
                *reinterpret_cast<const uint4*>(Qb + (size_t)r * 1024 + c);
        }
        __syncthreads();                 // Qsh (and first-iter Csh) visible

        // fp32 normalizer: zinv[t] = 1/(q[t,:] . ksum + 1e-6)
        if (tid < 64) {
            float s = 0.f;
            #pragma unroll 16
            for (int d = 0; d < 64; d++)
                s += __half2float(Qsh[tid * 72 + d]) * ksf[d];
            zinv[tid] = 1.f / (s + 1e-6f);
        }

        wmma::fragment<wmma::accumulator,16,16,16,float> acc[4];
        #pragma unroll
        for (int j = 0; j < 4; j++) wmma::fill_fragment(acc[j], 0.f);

        #pragma unroll
        for (int k = 0; k < 4; k++) {
            wmma::fragment<wmma::matrix_a,16,16,16,__half,wmma::row_major> af;
            wmma::load_matrix_sync(af, &Qsh[(warp * 16) * 72 + k * 16], 72);
            #pragma unroll
            for (int j = 0; j < 4; j++) {
                wmma::fragment<wmma::matrix_b,16,16,16,__half,wmma::row_major> bf;
                wmma::load_matrix_sync(bf, &Csh[(k * 16) * 72 + j * 16], 72);
                wmma::mma_sync(acc[j], af, bf, acc[j]);
            }
        }
        __syncthreads();                 // zinv ready; Qsh reads done

        float* buf = Ep[warp];
        #pragma unroll
        for (int j = 0; j < 4; j++)
            wmma::store_matrix_sync(buf + j * 16, acc[j], 68, wmma::mem_row_major);
        __syncwarp();

        __half* Ob = g_Oh + (size_t)(b * T_ + tt * 64 + warp * 16) * 1024 + h * 64;
        #pragma unroll
        for (int t = lane; t < 16 * 64; t += 32) {
            int rr = t >> 6, cc = t & 63;
            float z = zinv[warp * 16 + rr];
            Ob[(size_t)rr * 1024 + cc] = __float2half_rn(buf[rr * 68 + cc] * z);
        }
    }
}

// ---------------------------------------------------------------------------
extern "C" void kernel_launch(void* const* d_in, const int* in_sizes, int n_in,
                              void* d_out, int out_size)
{
    const float* x  = (const float*)d_in[0];
    const float* Wq = (const float*)d_in[1];
    const float* bq = (const float*)d_in[2];
    const float* Wd = (const float*)d_in[3];
    const float* bd = (const float*)d_in[4];
    const float* Wu = (const float*)d_in[5];
    const float* bu = (const float*)d_in[6];
    const float* Wo = (const float*)d_in[7];
    const float* bo = (const float*)d_in[8];
    float* out = (float*)d_out;

    void *pXh, *pWfh, *pbqd, *pWuh, *pWoh, *pCh, *pOh;
    cudaGetSymbolAddress(&pXh,  g_Xh);
    cudaGetSymbolAddress(&pWfh, g_Wfh);
    cudaGetSymbolAddress(&pbqd, g_bqd);
    cudaGetSymbolAddress(&pWuh, g_Wuh);
    cudaGetSymbolAddress(&pWoh, g_Woh);
    cudaGetSymbolAddress(&pCh,  g_Ch);
    cudaGetSymbolAddress(&pOh,  g_Oh);

    cudaFuncSetAttribute(gemm_f16<0>, cudaFuncAttributeMaxDynamicSharedMemorySize, GEMM_SMEM);
    cudaFuncSetAttribute(gemm_f16<1>, cudaFuncAttributeMaxDynamicSharedMemorySize, GEMM_SMEM);
    cudaFuncSetAttribute(gemm_f16<2>, cudaFuncAttributeMaxDynamicSharedMemorySize, GEMM_SMEM);
    cudaFuncSetAttribute(ctx_kernel,  cudaFuncAttributeMaxDynamicSharedMemorySize, CTX_SMEM);

    prep_kernel<<<PREP_BLOCKS, 256>>>(x, Wq, Wd, Wu, Wo, bq, bd);

    // [Q|C] = x @ [Wq|Wd] + [bq|bd], elu+1 on Q half.  grid: (N tiles, M tiles)
    gemm_f16<0><<<dim3(1280/BN, M_/BM), 256, GEMM_SMEM>>>(
        (const __half*)pXh, (const __half*)pWfh, (const float*)pbqd, nullptr, 1280, 1024);
    // KV = C@Wu + bu, elu+1 on k half of each head
    gemm_f16<1><<<dim3(2048/BN, M_/BM), 256, GEMM_SMEM>>>(
        (const __half*)pCh, (const __half*)pWuh, bu, nullptr, 2048, 256);

    ctx_kernel<<<dim3(64, 8), 128, CTX_SMEM>>>();
    attn_out_kernel<<<dim3(64, 16), 128>>>();

    // out = O@Wo + bo
    gemm_f16<2><<<dim3(1024/BN, M_/BM), 256, GEMM_SMEM>>>(
        (const __half*)pOh, (const __half*)pWoh, bo, out, 1024, 1024);
}

// round 14
// speedup vs baseline: 5.6422x; 1.0046x over previous
#include <cuda_runtime.h>
#include <cstdint>
#include <cuda_fp16.h>
#include <mma.h>
using namespace nvcuda;

// Problem constants
#define B_  4
#define T_  4096
#define D_  1024
#define H_  16
#define R_  256
#define DH_ 64
#define M_  16384   // B_*T_

// Scratch (allocation-free rule: __device__ globals)
__device__ __half g_Xh [16777216];  // x as fp16
__device__ __half g_Wfh[1310720];   // fused [Wq|Wd]  (1024 x 1280)
__device__ float  g_bqd[1280];      // fused bias [bq|bd]
__device__ __half g_Wuh[524288];
__device__ __half g_Woh[1048576];
__device__ __half g_Qh [16777216];  // (M,1024) q after elu+1
__device__ __half g_Ch [4194304];   // (M,256)  x@Wd+bd
__device__ __half g_KVh[33554432];  // (M,2048) kv, k-half elu+1'd
__device__ __half g_Oh [16777216];  // (M,1024) attention out * z
__device__ float  g_ctx[262144];    // (B*H,64,64)
__device__ float  g_ksum[4096];     // (B*H,64)

__device__ __forceinline__ void f4_to_h4(const float4 v, __half* dst) {
    __half2 h0 = __floats2half2_rn(v.x, v.y);
    __half2 h1 = __floats2half2_rn(v.z, v.w);
    uint2 u;
    u.x = *reinterpret_cast<unsigned*>(&h0);
    u.y = *reinterpret_cast<unsigned*>(&h1);
    *reinterpret_cast<uint2*>(dst) = u;
}

// ---------------------------------------------------------------------------
// Fused prep: zero ctx/ksum, x->fp16, build [Wq|Wd] fp16 + fused bias,
// convert Wu/Wo. Segments in float4 units.
// ---------------------------------------------------------------------------
#define P_X    4194304
#define P_WF   (P_X + 327680)       // 4521984
#define P_WU   (P_WF + 131072)      // 4653056
#define P_WO   (P_WU + 262144)      // 4915200
#define P_BIAS (P_WO + 320)         // 4915520
#define P_CTX  (P_BIAS + 65536)     // 4981056
#define P_KS   (P_CTX + 1024)       // 4982080
#define PREP_BLOCKS ((P_KS + 255) / 256)

__global__ void prep_kernel(const float* __restrict__ x,
                            const float* __restrict__ Wq, const float* __restrict__ Wd,
                            const float* __restrict__ Wu, const float* __restrict__ Wo,
                            const float* __restrict__ bq, const float* __restrict__ bd) {
    int i = blockIdx.x * blockDim.x + threadIdx.x;
    if (i < P_X) {
        float4 v = reinterpret_cast<const float4*>(x)[i];
        f4_to_h4(v, &g_Xh[(size_t)i * 4]);
    } else if (i < P_WF) {
        int e = (i - P_X) * 4, r = e / 1280, c = e % 1280;
        float4 v = (c < 1024)
            ? *reinterpret_cast<const float4*>(&Wq[(size_t)r * 1024 + c])
            : *reinterpret_cast<const float4*>(&Wd[(size_t)r * 256 + c - 1024]);
        f4_to_h4(v, &g_Wfh[e]);
    } else if (i < P_WU) {
        int j = i - P_WF;
        float4 v = reinterpret_cast<const float4*>(Wu)[j];
        f4_to_h4(v, &g_Wuh[(size_t)j * 4]);
    } else if (i < P_WO) {
        int j = i - P_WU;
        float4 v = reinterpret_cast<const float4*>(Wo)[j];
        f4_to_h4(v, &g_Woh[(size_t)j * 4]);
    } else if (i < P_BIAS) {
        int e = (i - P_WO) * 4;
        float4 v = (e < 1024)
            ? *reinterpret_cast<const float4*>(&bq[e])
            : *reinterpret_cast<const float4*>(&bd[e - 1024]);
        *reinterpret_cast<float4*>(&g_bqd[e]) = v;
    } else if (i < P_CTX) {
        int j = i - P_BIAS;
        reinterpret_cast<float4*>(g_ctx)[j] = make_float4(0.f, 0.f, 0.f, 0.f);
    } else if (i < P_KS) {
        int j = i - P_CTX;
        reinterpret_cast<float4*>(g_ksum)[j] = make_float4(0.f, 0.f, 0.f, 0.f);
    }
}

// ---------------------------------------------------------------------------
// cp.async helpers
// ---------------------------------------------------------------------------
__device__ __forceinline__ void cp16(void* smem_dst, const void* gmem_src) {
    unsigned s = (unsigned)__cvta_generic_to_shared(smem_dst);
    asm volatile("cp.async.cg.shared.global [%0], [%1], 16;\n" :: "r"(s), "l"(gmem_src));
}
__device__ __forceinline__ void cp_commit() {
    asm volatile("cp.async.commit_group;\n" ::: "memory");
}
template<int N>
__device__ __forceinline__ void cp_wait() {
    asm volatile("cp.async.wait_group %0;\n" :: "n"(N) : "memory");
}

// ---------------------------------------------------------------------------
// fp16 WMMA GEMM. CTA tile 128x128x64, warp tile 32x64 (4x2 warps),
// 3-stage cp.async pipeline, ONE syncthreads per k-iter, 2 CTAs/SM.
// Inner loop: ALL fragment loads (2 af + 4 bf) hoisted ahead of the 8 mma
// per kk to lengthen the LDSM->HMMA dependency distance.
// MODE 0: fused QD (cols<1024: elu+1 -> g_Qh; else -> g_Ch)
// MODE 1: KV (elu+1 where (col&127)<64 -> g_KVh)
// MODE 2: plain float out (final)
// ---------------------------------------------------------------------------
#define BM 128
#define BN 128
#define BK 64
#define LDAh 72
#define LDBh 136
#define STAGE_Ah (BM * LDAh)   // 9216 halves
#define STAGE_Bh (BK * LDBh)   // 8704 halves
#define NSTAGE 3
#define GEMM_SMEM (NSTAGE * (STAGE_Ah + STAGE_Bh) * 2)   // 107520 B

template<int MODE>
__global__ __launch_bounds__(256, 2)
void gemm_f16(const __half* __restrict__ A, const __half* __restrict__ Bm,
              const float* __restrict__ bias, float* __restrict__ CoutF,
              int Ndim, int Kdim)
{
    extern __shared__ __half smh[];
    __half* Asm = smh;
    __half* Bsm = smh + NSTAGE * STAGE_Ah;

    const int tid  = threadIdx.x;
    const int warp = tid >> 5;
    const int lane = tid & 31;
    const int wm = warp >> 1;               // 0..3
    const int wn = warp & 1;                // 0..1
    const int row0 = blockIdx.y * BM;
    const int col0 = blockIdx.x * BN;
    const int Ktiles = Kdim / BK;

    // Hoisted per-thread staging offsets (constant across the k-loop).
    const unsigned a_soff = (unsigned)(tid >> 3) * LDAh + (tid & 7) * 8;
    const size_t   a_goff = (size_t)(tid >> 3) * Kdim + (tid & 7) * 8;
    const unsigned b_soff = (unsigned)(tid >> 4) * LDBh + (tid & 15) * 8;
    const size_t   b_goff = (size_t)(tid >> 4) * Ndim + (tid & 15) * 8;
    const __half* Abase = A + (size_t)row0 * Kdim + a_goff;
    const __half* Bbase = Bm + col0 + b_goff;

    auto issue = [&](int stage, int kt) {
        __half* as = Asm + stage * STAGE_Ah + a_soff;
        __half* bs = Bsm + stage * STAGE_Bh + b_soff;
        const __half* Ag = Abase + (size_t)kt * BK;
        const __half* Bg = Bbase + (size_t)kt * BK * Ndim;
        #pragma unroll
        for (int p = 0; p < 4; p++)          // A: 128 rows, 32/step
            cp16(as + p * 32 * LDAh, Ag + (size_t)p * 32 * Kdim);
        #pragma unroll
        for (int p = 0; p < 4; p++)          // B: 64 rows, 16/step
            cp16(bs + p * 16 * LDBh, Bg + (size_t)p * 16 * Ndim);
        cp_commit();
    };

    wmma::fragment<wmma::accumulator,16,16,16,float> acc[2][4];
    #pragma unroll
    for (int i = 0; i < 2; i++)
        #pragma unroll
        for (int j = 0; j < 4; j++) wmma::fill_fragment(acc[i][j], 0.f);

    issue(0, 0);
    if (Ktiles > 1) issue(1, 1);

    for (int kt = 0; kt < Ktiles; kt++) {
        if (kt + 1 < Ktiles) cp_wait<1>(); else cp_wait<0>();
        __syncthreads();

        const __half* as = Asm + (kt % NSTAGE) * STAGE_Ah;
        const __half* bs = Bsm + (kt % NSTAGE) * STAGE_Bh;

        #pragma unroll
        for (int kk = 0; kk < 4; kk++) {     // 4 x k=16
            wmma::fragment<wmma::matrix_a,16,16,16,__half,wmma::row_major> af[2];
            wmma::fragment<wmma::matrix_b,16,16,16,__half,wmma::row_major> bf[4];
            #pragma unroll
            for (int i = 0; i < 2; i++)
                wmma::load_matrix_sync(af[i], &as[(wm*32 + i*16)*LDAh + kk*16], LDAh);
            #pragma unroll
            for (int j = 0; j < 4; j++)
                wmma::load_matrix_sync(bf[j], &bs[(kk*16)*LDBh + wn*64 + j*16], LDBh);
            #pragma unroll
            for (int j = 0; j < 4; j++)
                #pragma unroll
                for (int i = 0; i < 2; i++)
                    wmma::mma_sync(acc[i][j], af[i], bf[j], acc[i][j]);
        }

        if (kt + 2 < Ktiles) issue((kt + 2) % NSTAGE, kt + 2);
    }

    __syncthreads();   // all warps done reading pipeline smem

    // Epilogue: per-warp float staging (32x68), then float4 stores.
    float* ep = reinterpret_cast<float*>(smh) + warp * (32 * 68);   // 69632B total
    #pragma unroll
    for (int ii = 0; ii < 2; ii++)
        #pragma unroll
        for (int j = 0; j < 4; j++)
            wmma::store_matrix_sync(ep + (ii*16)*68 + j*16, acc[ii][j], 68,
                                    wmma::mem_row_major);
    __syncwarp();

    const int gr0 = row0 + wm * 32;
    const int gc0 = col0 + wn * 64;
    #pragma unroll
    for (int idx = lane; idx < 512; idx += 32) {   // 32 rows x 16 float4
        int rr = idx >> 4, c4 = (idx & 15) * 4;
        int gc = gc0 + c4;
        float4 v = *reinterpret_cast<const float4*>(&ep[rr*68 + c4]);
        float4 bb = *reinterpret_cast<const float4*>(&bias[gc]);
        v.x += bb.x; v.y += bb.y; v.z += bb.z; v.w += bb.w;
        int gr = gr0 + rr;
        if (MODE == 0) {
            if (gc < 1024) {
                v.x = (v.x > 0.f) ? v.x + 1.f : __expf(v.x);
                v.y = (v.y > 0.f) ? v.y + 1.f : __expf(v.y);
                v.z = (v.z > 0.f) ? v.z + 1.f : __expf(v.z);
                v.w = (v.w > 0.f) ? v.w + 1.f : __expf(v.w);
                f4_to_h4(v, &g_Qh[(size_t)gr * 1024 + gc]);
            } else {
                f4_to_h4(v, &g_Ch[(size_t)gr * 256 + (gc - 1024)]);
            }
        } else if (MODE == 1) {
            if ((gc & 127) < 64) {
                v.x = (v.x > 0.f) ? v.x + 1.f : __expf(v.x);
                v.y = (v.y > 0.f) ? v.y + 1.f : __expf(v.y);
                v.z = (v.z > 0.f) ? v.z + 1.f : __expf(v.z);
                v.w = (v.w > 0.f) ? v.w + 1.f : __expf(v.w);
            }
            f4_to_h4(v, &g_KVh[(size_t)gr * 2048 + gc]);
        } else {
            *reinterpret_cast<float4*>(&CoutF[(size_t)gr * Ndim + gc]) = v;
        }
    }
}

// ---------------------------------------------------------------------------
// ctx[b,h] = sum_t k[t,:]^T v[t,:] (64x64) + ksum. Smem-staged via cp.async,
// 2-stage, fp16 LDSM fragments. grid (64 bh, 16 splits), block 128 (4 warps).
// Each split covers 256 tokens = 2 chunks of 128.
// ---------------------------------------------------------------------------
#define CTX_LD 136
#define CTX_STAGE (128 * CTX_LD)                  // halves
#define CTX_SMEM (2 * CTX_STAGE * 2)              // 69632 B dynamic
#define CTX_SPLITS 16
#define CTX_CHUNKS 2                              // 512/CTX_SPLITS/... tokens: 256/128

__global__ __launch_bounds__(128)
void ctx_kernel()
{
    extern __shared__ __half kvs[];
    const int bh = blockIdx.x;           // 0..63
    const int split = blockIdx.y;        // 0..15
    const int b = bh >> 4, h = bh & 15;
    const __half* Kb = g_KVh + (size_t)b * T_ * 2048 + h * 128;  // k|v 128 halves
    const int tid  = threadIdx.x;
    const int warp = tid >> 5, lane = tid & 31;
    const int tbase = split * (T_ / CTX_SPLITS);   // 256 tokens per split

    auto issue = [&](int stage, int c) {
        __half* s = kvs + stage * CTX_STAGE;
        const __half* g = Kb + (size_t)(tbase + c * 128) * 2048;
        #pragma unroll
        for (int p = 0; p < 16; p++) {    // 2048 chunks of 8 halves
            int ci = tid + p * 128;
            int r = ci >> 4, cc = (ci & 15) * 8;
            cp16(&s[r * CTX_LD + cc], g + (size_t)r * 2048 + cc);
        }
    };

    wmma::fragment<wmma::accumulator,16,16,16,float> acc[4];
    #pragma unroll
    for (int j = 0; j < 4; j++) wmma::fill_fragment(acc[j], 0.f);
    float ks = 0.f;
    const int kd = tid & 63, kgrp = tid >> 6;   // ksum: 2 groups x 64 tokens

    issue(0, 0); cp_commit();

    for (int c = 0; c < CTX_CHUNKS; c++) {
        if (c + 1 < CTX_CHUNKS) { issue((c + 1) & 1, c + 1); cp_commit(); cp_wait<1>(); }
        else cp_wait<0>();
        __syncthreads();

        const __half* s = kvs + (c & 1) * CTX_STAGE;
        #pragma unroll
        for (int k8 = 0; k8 < 8; k8++) {
            int t0 = k8 * 16;
            wmma::fragment<wmma::matrix_a,16,16,16,__half,wmma::col_major> af;
            wmma::load_matrix_sync(af, &s[t0 * CTX_LD + warp * 16], CTX_LD);
            #pragma unroll
            for (int j = 0; j < 4; j++) {
                wmma::fragment<wmma::matrix_b,16,16,16,__half,wmma::row_major> bf;
                wmma::load_matrix_sync(bf, &s[t0 * CTX_LD + 64 + j * 16], CTX_LD);
                wmma::mma_sync(acc[j], af, bf, acc[j]);
            }
        }
        // ksum partial from smem (K cols 0..63)
        #pragma unroll 8
        for (int t = kgrp * 64; t < kgrp * 64 + 64; t++)
            ks += __half2float(s[t * CTX_LD + kd]);
        __syncthreads();
    }

    __shared__ float cep[4][16 * 68];
    float* buf = cep[warp];
    #pragma unroll
    for (int j = 0; j < 4; j++)
        wmma::store_matrix_sync(buf + j * 16, acc[j], 68, wmma::mem_row_major);
    __syncwarp();

    float* ctxp = g_ctx + bh * 4096;
    #pragma unroll
    for (int t = lane; t < 16 * 64; t += 32) {
        int rr = t >> 6, cc = t & 63;
        atomicAdd(&ctxp[(warp * 16 + rr) * 64 + cc], buf[rr * 68 + cc]);
    }
    atomicAdd(&g_ksum[bh * 64 + kd], ks);
}

// ---------------------------------------------------------------------------
// out = (q @ ctx) * 1/(q . ksum + 1e-6).  fp16 WMMA; normalizer in fp32.
// Block handles 256 tokens (4 tiles of 64) for one (b,h): ctx loaded once.
// grid (64 bh, 16 groups), block 128.
// ---------------------------------------------------------------------------
__global__ __launch_bounds__(128)
void attn_out_kernel()
{
    const int bh = blockIdx.x;
    const int grp = blockIdx.y;          // 0..15, each 256 tokens
    const int b = bh >> 4, h = bh & 15;
    const int tid = threadIdx.x;
    const int warp = tid >> 5, lane = tid & 31;

    __shared__ __half Qsh[64 * 72];
    __shared__ __half Csh[64 * 72];
    __shared__ float  ksf[64];
    __shared__ float  zinv[64];
    __shared__ float  Ep[4][16 * 68];

    // Load ctx + ksum once per block.
    const float* cp = g_ctx + bh * 4096;
    for (int i = tid; i < 4096; i += 128) {
        int d = i >> 6, e = i & 63;
        Csh[d * 72 + e] = __float2half_rn(cp[i]);
    }
    if (tid < 64) ksf[tid] = g_ksum[bh * 64 + tid];

    for (int sub = 0; sub < 4; sub++) {
        int tt = grp * 4 + sub;          // 64-token tile index
        __syncthreads();                 // prior iter's zinv/Qsh reads done

        const __half* Qb = g_Qh + (size_t)(b * T_ + tt * 64) * 1024 + h * 64;
        #pragma unroll
        for (int p = 0; p < 4; p++) {    // 512 chunks of 8 halves (16B each)
            int idx = tid + p * 128;
            int r = idx >> 3, c = (idx & 7) * 8;
            *reinterpret_cast<uint4*>(&Qsh[r * 72 + c]) =
                *reinterpret_cast<const uint4*>(Qb + (size_t)r * 1024 + c);
        }
        __syncthreads();                 // Qsh (and first-iter Csh) visible

        // fp32 normalizer: zinv[t] = 1/(q[t,:] . ksum + 1e-6)
        if (tid < 64) {
            float s = 0.f;
            #pragma unroll 16
            for (int d = 0; d < 64; d++)
                s += __half2float(Qsh[tid * 72 + d]) * ksf[d];
            zinv[tid] = 1.f / (s + 1e-6f);
        }

        wmma::fragment<wmma::accumulator,16,16,16,float> acc[4];
        #pragma unroll
        for (int j = 0; j < 4; j++) wmma::fill_fragment(acc[j], 0.f);

        #pragma unroll
        for (int k = 0; k < 4; k++) {
            wmma::fragment<wmma::matrix_a,16,16,16,__half,wmma::row_major> af;
            wmma::load_matrix_sync(af, &Qsh[(warp * 16) * 72 + k * 16], 72);
            #pragma unroll
            for (int j = 0; j < 4; j++) {
                wmma::fragment<wmma::matrix_b,16,16,16,__half,wmma::row_major> bf;
                wmma::load_matrix_sync(bf, &Csh[(k * 16) * 72 + j * 16], 72);
                wmma::mma_sync(acc[j], af, bf, acc[j]);
            }
        }
        __syncthreads();                 // zinv ready; Qsh reads done

        float* buf = Ep[warp];
        #pragma unroll
        for (int j = 0; j < 4; j++)
            wmma::store_matrix_sync(buf + j * 16, acc[j], 68, wmma::mem_row_major);
        __syncwarp();

        __half* Ob = g_Oh + (size_t)(b * T_ + tt * 64 + warp * 16) * 1024 + h * 64;
        #pragma unroll
        for (int t = lane; t < 16 * 64; t += 32) {
            int rr = t >> 6, cc = t & 63;
            float z = zinv[warp * 16 + rr];
            Ob[(size_t)rr * 1024 + cc] = __float2half_rn(buf[rr * 68 + cc] * z);
        }
    }
}

// ---------------------------------------------------------------------------
extern "C" void kernel_launch(void* const* d_in, const int* in_sizes, int n_in,
                              void* d_out, int out_size)
{
    const float* x  = (const float*)d_in[0];
    const float* Wq = (const float*)d_in[1];
    const float* bq = (const float*)d_in[2];
    const float* Wd = (const float*)d_in[3];
    const float* bd = (const float*)d_in[4];
    const float* Wu = (const float*)d_in[5];
    const float* bu = (const float*)d_in[6];
    const float* Wo = (const float*)d_in[7];
    const float* bo = (const float*)d_in[8];
    float* out = (float*)d_out;

    void *pXh, *pWfh, *pbqd, *pWuh, *pWoh, *pCh, *pOh;
    cudaGetSymbolAddress(&pXh,  g_Xh);
    cudaGetSymbolAddress(&pWfh, g_Wfh);
    cudaGetSymbolAddress(&pbqd, g_bqd);
    cudaGetSymbolAddress(&pWuh, g_Wuh);
    cudaGetSymbolAddress(&pWoh, g_Woh);
    cudaGetSymbolAddress(&pCh,  g_Ch);
    cudaGetSymbolAddress(&pOh,  g_Oh);

    cudaFuncSetAttribute(gemm_f16<0>, cudaFuncAttributeMaxDynamicSharedMemorySize, GEMM_SMEM);
    cudaFuncSetAttribute(gemm_f16<1>, cudaFuncAttributeMaxDynamicSharedMemorySize, GEMM_SMEM);
    cudaFuncSetAttribute(gemm_f16<2>, cudaFuncAttributeMaxDynamicSharedMemorySize, GEMM_SMEM);
    cudaFuncSetAttribute(ctx_kernel,  cudaFuncAttributeMaxDynamicSharedMemorySize, CTX_SMEM);

    prep_kernel<<<PREP_BLOCKS, 256>>>(x, Wq, Wd, Wu, Wo, bq, bd);

    // [Q|C] = x @ [Wq|Wd] + [bq|bd], elu+1 on Q half.  grid: (N tiles, M tiles)
    gemm_f16<0><<<dim3(1280/BN, M_/BM), 256, GEMM_SMEM>>>(
        (const __half*)pXh, (const __half*)pWfh, (const float*)pbqd, nullptr, 1280, 1024);
    // KV = C@Wu + bu, elu+1 on k half of each head
    gemm_f16<1><<<dim3(2048/BN, M_/BM), 256, GEMM_SMEM>>>(
        (const __half*)pCh, (const __half*)pWuh, bu, nullptr, 2048, 256);

    ctx_kernel<<<dim3(64, CTX_SPLITS), 128, CTX_SMEM>>>();
    attn_out_kernel<<<dim3(64, 16), 128>>>();

    // out = O@Wo + bo
    gemm_f16<2><<<dim3(1024/BN, M_/BM), 256, GEMM_SMEM>>>(
        (const __half*)pOh, (const __half*)pWoh, bo, out, 1024, 1024);
}

// round 15
// speedup vs baseline: 5.8886x; 1.0437x over previous
#include <cuda_runtime.h>
#include <cstdint>
#include <cuda_fp16.h>
#include <mma.h>
using namespace nvcuda;

// Problem constants
#define B_  4
#define T_  4096
#define D_  1024
#define H_  16
#define R_  256
#define DH_ 64
#define M_  16384   // B_*T_

// Scratch (allocation-free rule: __device__ globals)
__device__ __half g_Xh [16777216];  // x as fp16
__device__ __half g_Wfh[1310720];   // fused [Wq|Wd]  (1024 x 1280)
__device__ float  g_bqd[1280];      // fused bias [bq|bd]
__device__ __half g_Wuh[524288];
__device__ __half g_Woh[1048576];
__device__ __half g_Qh [16777216];  // (M,1024) q after elu+1
__device__ __half g_Ch [4194304];   // (M,256)  x@Wd+bd
__device__ __half g_Oh [16777216];  // (M,1024) attention out * z
__device__ float  g_ctx[262144];    // (B*H,64,64)
__device__ float  g_ksum[4096];     // (B*H,64)

__device__ __forceinline__ void f4_to_h4(const float4 v, __half* dst) {
    __half2 h0 = __floats2half2_rn(v.x, v.y);
    __half2 h1 = __floats2half2_rn(v.z, v.w);
    uint2 u;
    u.x = *reinterpret_cast<unsigned*>(&h0);
    u.y = *reinterpret_cast<unsigned*>(&h1);
    *reinterpret_cast<uint2*>(dst) = u;
}

// ---------------------------------------------------------------------------
// Fused prep: zero ctx/ksum, x->fp16, build [Wq|Wd] fp16 + fused bias,
// convert Wu/Wo. Segments in float4 units.
// ---------------------------------------------------------------------------
#define P_X    4194304
#define P_WF   (P_X + 327680)       // 4521984
#define P_WU   (P_WF + 131072)      // 4653056
#define P_WO   (P_WU + 262144)      // 4915200
#define P_BIAS (P_WO + 320)         // 4915520
#define P_CTX  (P_BIAS + 65536)     // 4981056
#define P_KS   (P_CTX + 1024)       // 4982080
#define PREP_BLOCKS ((P_KS + 255) / 256)

__global__ void prep_kernel(const float* __restrict__ x,
                            const float* __restrict__ Wq, const float* __restrict__ Wd,
                            const float* __restrict__ Wu, const float* __restrict__ Wo,
                            const float* __restrict__ bq, const float* __restrict__ bd) {
    int i = blockIdx.x * blockDim.x + threadIdx.x;
    if (i < P_X) {
        float4 v = reinterpret_cast<const float4*>(x)[i];
        f4_to_h4(v, &g_Xh[(size_t)i * 4]);
    } else if (i < P_WF) {
        int e = (i - P_X) * 4, r = e / 1280, c = e % 1280;
        float4 v = (c < 1024)
            ? *reinterpret_cast<const float4*>(&Wq[(size_t)r * 1024 + c])
            : *reinterpret_cast<const float4*>(&Wd[(size_t)r * 256 + c - 1024]);
        f4_to_h4(v, &g_Wfh[e]);
    } else if (i < P_WU) {
        int j = i - P_WF;
        float4 v = reinterpret_cast<const float4*>(Wu)[j];
        f4_to_h4(v, &g_Wuh[(size_t)j * 4]);
    } else if (i < P_WO) {
        int j = i - P_WU;
        float4 v = reinterpret_cast<const float4*>(Wo)[j];
        f4_to_h4(v, &g_Woh[(size_t)j * 4]);
    } else if (i < P_BIAS) {
        int e = (i - P_WO) * 4;
        float4 v = (e < 1024)
            ? *reinterpret_cast<const float4*>(&bq[e])
            : *reinterpret_cast<const float4*>(&bd[e - 1024]);
        *reinterpret_cast<float4*>(&g_bqd[e]) = v;
    } else if (i < P_CTX) {
        int j = i - P_BIAS;
        reinterpret_cast<float4*>(g_ctx)[j] = make_float4(0.f, 0.f, 0.f, 0.f);
    } else if (i < P_KS) {
        int j = i - P_CTX;
        reinterpret_cast<float4*>(g_ksum)[j] = make_float4(0.f, 0.f, 0.f, 0.f);
    }
}

// ---------------------------------------------------------------------------
// cp.async helpers
// ---------------------------------------------------------------------------
__device__ __forceinline__ void cp16(void* smem_dst, const void* gmem_src) {
    unsigned s = (unsigned)__cvta_generic_to_shared(smem_dst);
    asm volatile("cp.async.cg.shared.global [%0], [%1], 16;\n" :: "r"(s), "l"(gmem_src));
}
__device__ __forceinline__ void cp_commit() {
    asm volatile("cp.async.commit_group;\n" ::: "memory");
}
template<int N>
__device__ __forceinline__ void cp_wait() {
    asm volatile("cp.async.wait_group %0;\n" :: "n"(N) : "memory");
}

// ---------------------------------------------------------------------------
// fp16 WMMA GEMM. CTA tile 128x128x64, warp tile 32x64 (4x2 warps),
// 3-stage cp.async pipeline, ONE syncthreads per k-iter, 2 CTAs/SM.
// MODE 0: fused QD (cols<1024: elu+1 -> g_Qh; else -> g_Ch)
// MODE 1: KV+ctx fusion. CTA tile = 128 tokens x one head's [k|v].
//         Epilogue: bias+elu(k), fp16 tile in smem, then k^T v (64x64x128)
//         + ksum reduced IN-KERNEL via atomicAdd into g_ctx/g_ksum.
//         KV is never written to global.
// MODE 2: plain float out (final)
// ---------------------------------------------------------------------------
#define BM 128
#define BN 128
#define BK 64
#define LDAh 72
#define LDBh 136
#define STAGE_Ah (BM * LDAh)   // 9216 halves
#define STAGE_Bh (BK * LDBh)   // 8704 halves
#define NSTAGE 3
#define GEMM_SMEM (NSTAGE * (STAGE_Ah + STAGE_Bh) * 2)   // 107520 B
#define KV_LD 136              // halves; 128x136 fp16 tile = 34816 B

template<int MODE>
__global__ __launch_bounds__(256, 2)
void gemm_f16(const __half* __restrict__ A, const __half* __restrict__ Bm,
              const float* __restrict__ bias, float* __restrict__ CoutF,
              int Ndim, int Kdim)
{
    extern __shared__ __half smh[];
    __half* Asm = smh;
    __half* Bsm = smh + NSTAGE * STAGE_Ah;

    const int tid  = threadIdx.x;
    const int warp = tid >> 5;
    const int lane = tid & 31;
    const int wm = warp >> 1;               // 0..3
    const int wn = warp & 1;                // 0..1
    const int row0 = blockIdx.y * BM;
    const int col0 = blockIdx.x * BN;
    const int Ktiles = Kdim / BK;

    // Hoisted per-thread staging offsets (constant across the k-loop).
    const unsigned a_soff = (unsigned)(tid >> 3) * LDAh + (tid & 7) * 8;
    const size_t   a_goff = (size_t)(tid >> 3) * Kdim + (tid & 7) * 8;
    const unsigned b_soff = (unsigned)(tid >> 4) * LDBh + (tid & 15) * 8;
    const size_t   b_goff = (size_t)(tid >> 4) * Ndim + (tid & 15) * 8;
    const __half* Abase = A + (size_t)row0 * Kdim + a_goff;
    const __half* Bbase = Bm + col0 + b_goff;

    auto issue = [&](int stage, int kt) {
        __half* as = Asm + stage * STAGE_Ah + a_soff;
        __half* bs = Bsm + stage * STAGE_Bh + b_soff;
        const __half* Ag = Abase + (size_t)kt * BK;
        const __half* Bg = Bbase + (size_t)kt * BK * Ndim;
        #pragma unroll
        for (int p = 0; p < 4; p++)          // A: 128 rows, 32/step
            cp16(as + p * 32 * LDAh, Ag + (size_t)p * 32 * Kdim);
        #pragma unroll
        for (int p = 0; p < 4; p++)          // B: 64 rows, 16/step
            cp16(bs + p * 16 * LDBh, Bg + (size_t)p * 16 * Ndim);
        cp_commit();
    };

    wmma::fragment<wmma::accumulator,16,16,16,float> acc[2][4];
    #pragma unroll
    for (int i = 0; i < 2; i++)
        #pragma unroll
        for (int j = 0; j < 4; j++) wmma::fill_fragment(acc[i][j], 0.f);

    issue(0, 0);
    if (Ktiles > 1) issue(1, 1);

    for (int kt = 0; kt < Ktiles; kt++) {
        if (kt + 1 < Ktiles) cp_wait<1>(); else cp_wait<0>();
        __syncthreads();

        const __half* as = Asm + (kt % NSTAGE) * STAGE_Ah;
        const __half* bs = Bsm + (kt % NSTAGE) * STAGE_Bh;

        #pragma unroll
        for (int kk = 0; kk < 4; kk++) {     // 4 x k=16
            wmma::fragment<wmma::matrix_a,16,16,16,__half,wmma::row_major> af[2];
            wmma::fragment<wmma::matrix_b,16,16,16,__half,wmma::row_major> bf[4];
            #pragma unroll
            for (int i = 0; i < 2; i++)
                wmma::load_matrix_sync(af[i], &as[(wm*32 + i*16)*LDAh + kk*16], LDAh);
            #pragma unroll
            for (int j = 0; j < 4; j++)
                wmma::load_matrix_sync(bf[j], &bs[(kk*16)*LDBh + wn*64 + j*16], LDBh);
            #pragma unroll
            for (int j = 0; j < 4; j++)
                #pragma unroll
                for (int i = 0; i < 2; i++)
                    wmma::mma_sync(acc[i][j], af[i], bf[j], acc[i][j]);
        }

        if (kt + 2 < Ktiles) issue((kt + 2) % NSTAGE, kt + 2);
    }

    __syncthreads();   // all warps done reading pipeline smem

    if (MODE != 1) {
        // Epilogue: per-warp float staging (32x68), then float4 stores.
        float* ep = reinterpret_cast<float*>(smh) + warp * (32 * 68);
        #pragma unroll
        for (int ii = 0; ii < 2; ii++)
            #pragma unroll
            for (int j = 0; j < 4; j++)
                wmma::store_matrix_sync(ep + (ii*16)*68 + j*16, acc[ii][j], 68,
                                        wmma::mem_row_major);
        __syncwarp();

        const int gr0 = row0 + wm * 32;
        const int gc0 = col0 + wn * 64;
        #pragma unroll
        for (int idx = lane; idx < 512; idx += 32) {   // 32 rows x 16 float4
            int rr = idx >> 4, c4 = (idx & 15) * 4;
            int gc = gc0 + c4;
            float4 v = *reinterpret_cast<const float4*>(&ep[rr*68 + c4]);
            float4 bb = *reinterpret_cast<const float4*>(&bias[gc]);
            v.x += bb.x; v.y += bb.y; v.z += bb.z; v.w += bb.w;
            int gr = gr0 + rr;
            if (MODE == 0) {
                if (gc < 1024) {
                    v.x = (v.x > 0.f) ? v.x + 1.f : __expf(v.x);
                    v.y = (v.y > 0.f) ? v.y + 1.f : __expf(v.y);
                    v.z = (v.z > 0.f) ? v.z + 1.f : __expf(v.z);
                    v.w = (v.w > 0.f) ? v.w + 1.f : __expf(v.w);
                    f4_to_h4(v, &g_Qh[(size_t)gr * 1024 + gc]);
                } else {
                    f4_to_h4(v, &g_Ch[(size_t)gr * 256 + (gc - 1024)]);
                }
            } else {
                *reinterpret_cast<float4*>(&CoutF[(size_t)gr * Ndim + gc]) = v;
            }
        }
    } else {
        // ---- MODE 1: KV tile -> smem fp16 + fused ctx/ksum reduction ----
        __half* KVs = smh;                                      // 128 x KV_LD
        float* ep = reinterpret_cast<float*>(
                        reinterpret_cast<char*>(smh) + 128 * KV_LD * 2)
                    + warp * (32 * 68);                         // 34816 + 69632 B

        #pragma unroll
        for (int ii = 0; ii < 2; ii++)
            #pragma unroll
            for (int j = 0; j < 4; j++)
                wmma::store_matrix_sync(ep + (ii*16)*68 + j*16, acc[ii][j], 68,
                                        wmma::mem_row_major);
        __syncwarp();

        const int gc0 = col0 + wn * 64;
        #pragma unroll
        for (int idx = lane; idx < 512; idx += 32) {   // 32 rows x 16 float4
            int rr = idx >> 4, c4 = (idx & 15) * 4;
            int lc = wn * 64 + c4;                      // local col 0..127
            float4 v = *reinterpret_cast<const float4*>(&ep[rr*68 + c4]);
            float4 bb = *reinterpret_cast<const float4*>(&bias[gc0 + c4]);
            v.x += bb.x; v.y += bb.y; v.z += bb.z; v.w += bb.w;
            if (lc < 64) {                              // k half: elu+1
                v.x = (v.x > 0.f) ? v.x + 1.f : __expf(v.x);
                v.y = (v.y > 0.f) ? v.y + 1.f : __expf(v.y);
                v.z = (v.z > 0.f) ? v.z + 1.f : __expf(v.z);
                v.w = (v.w > 0.f) ? v.w + 1.f : __expf(v.w);
            }
            f4_to_h4(v, &KVs[(wm*32 + rr) * KV_LD + lc]);
        }
        __syncthreads();   // full [k|v] fp16 tile visible

        // ctx partial: K^T V, 64x64 over 128 tokens. 16 output tiles of
        // 16x16; warp w handles row tile (w>>1), col tiles (w&1)*2 + {0,1}.
        const int ti  = warp >> 1;
        const int tj0 = (warp & 1) * 2;
        wmma::fragment<wmma::accumulator,16,16,16,float> acc2[2];
        #pragma unroll
        for (int j = 0; j < 2; j++) wmma::fill_fragment(acc2[j], 0.f);
        #pragma unroll
        for (int ks = 0; ks < 8; ks++) {
            int t0 = ks * 16;
            wmma::fragment<wmma::matrix_a,16,16,16,__half,wmma::col_major> af2;
            wmma::load_matrix_sync(af2, &KVs[t0 * KV_LD + ti * 16], KV_LD);
            #pragma unroll
            for (int j = 0; j < 2; j++) {
                wmma::fragment<wmma::matrix_b,16,16,16,__half,wmma::row_major> bf2;
                wmma::load_matrix_sync(bf2, &KVs[t0 * KV_LD + 64 + (tj0 + j) * 16], KV_LD);
                wmma::mma_sync(acc2[j], af2, bf2, acc2[j]);
            }
        }

        // ksum partial: 4 groups of 32 tokens per d.
        const int kd = tid & 63, kq = tid >> 6;
        float kssum = 0.f;
        #pragma unroll 8
        for (int t = kq * 32; t < kq * 32 + 32; t++)
            kssum += __half2float(KVs[t * KV_LD + kd]);

        // Stage ctx partials and atomically reduce.
        float* buf = ep;
        wmma::store_matrix_sync(buf,      acc2[0], 68, wmma::mem_row_major);
        wmma::store_matrix_sync(buf + 16, acc2[1], 68, wmma::mem_row_major);
        __syncwarp();

        const int bh = (row0 >> 12) * 16 + (col0 >> 7);
        float* ctxp = g_ctx + bh * 4096;
        #pragma unroll
        for (int t = lane; t < 16 * 32; t += 32) {   // 16 rows x 32 cols
            int rr = t >> 5, cc = t & 31;
            atomicAdd(&ctxp[(ti * 16 + rr) * 64 + tj0 * 16 + cc], buf[rr * 68 + cc]);
        }
        atomicAdd(&g_ksum[bh * 64 + kd], kssum);
    }
}

// ---------------------------------------------------------------------------
// out = (q @ ctx) * 1/(q . ksum + 1e-6).  fp16 WMMA; normalizer in fp32.
// Block handles 256 tokens (4 tiles of 64) for one (b,h): ctx loaded once.
// grid (64 bh, 16 groups), block 128.
// ---------------------------------------------------------------------------
__global__ __launch_bounds__(128)
void attn_out_kernel()
{
    const int bh = blockIdx.x;
    const int grp = blockIdx.y;          // 0..15, each 256 tokens
    const int b = bh >> 4, h = bh & 15;
    const int tid = threadIdx.x;
    const int warp = tid >> 5, lane = tid & 31;

    __shared__ __half Qsh[64 * 72];
    __shared__ __half Csh[64 * 72];
    __shared__ float  ksf[64];
    __shared__ float  zinv[64];
    __shared__ float  Ep[4][16 * 68];

    // Load ctx + ksum once per block.
    const float* cp = g_ctx + bh * 4096;
    for (int i = tid; i < 4096; i += 128) {
        int d = i >> 6, e = i & 63;
        Csh[d * 72 + e] = __float2half_rn(cp[i]);
    }
    if (tid < 64) ksf[tid] = g_ksum[bh * 64 + tid];

    for (int sub = 0; sub < 4; sub++) {
        int tt = grp * 4 + sub;          // 64-token tile index
        __syncthreads();                 // prior iter's zinv/Qsh reads done

        const __half* Qb = g_Qh + (size_t)(b * T_ + tt * 64) * 1024 + h * 64;
        #pragma unroll
        for (int p = 0; p < 4; p++) {    // 512 chunks of 8 halves (16B each)
            int idx = tid + p * 128;
            int r = idx >> 3, c = (idx & 7) * 8;
            *reinterpret_cast<uint4*>(&Qsh[r * 72 + c]) =
                *reinterpret_cast<const uint4*>(Qb + (size_t)r * 1024 + c);
        }
        __syncthreads();                 // Qsh (and first-iter Csh) visible

        // fp32 normalizer: zinv[t] = 1/(q[t,:] . ksum + 1e-6)
        if (tid < 64) {
            float s = 0.f;
            #pragma unroll 16
            for (int d = 0; d < 64; d++)
                s += __half2float(Qsh[tid * 72 + d]) * ksf[d];
            zinv[tid] = 1.f / (s + 1e-6f);
        }

        wmma::fragment<wmma::accumulator,16,16,16,float> acc[4];
        #pragma unroll
        for (int j = 0; j < 4; j++) wmma::fill_fragment(acc[j], 0.f);

        #pragma unroll
        for (int k = 0; k < 4; k++) {
            wmma::fragment<wmma::matrix_a,16,16,16,__half,wmma::row_major> af;
            wmma::load_matrix_sync(af, &Qsh[(warp * 16) * 72 + k * 16], 72);
            #pragma unroll
            for (int j = 0; j < 4; j++) {
                wmma::fragment<wmma::matrix_b,16,16,16,__half,wmma::row_major> bf;
                wmma::load_matrix_sync(bf, &Csh[(k * 16) * 72 + j * 16], 72);
                wmma::mma_sync(acc[j], af, bf, acc[j]);
            }
        }
        __syncthreads();                 // zinv ready; Qsh reads done

        float* buf = Ep[warp];
        #pragma unroll
        for (int j = 0; j < 4; j++)
            wmma::store_matrix_sync(buf + j * 16, acc[j], 68, wmma::mem_row_major);
        __syncwarp();

        __half* Ob = g_Oh + (size_t)(b * T_ + tt * 64 + warp * 16) * 1024 + h * 64;
        #pragma unroll
        for (int t = lane; t < 16 * 64; t += 32) {
            int rr = t >> 6, cc = t & 63;
            float z = zinv[warp * 16 + rr];
            Ob[(size_t)rr * 1024 + cc] = __float2half_rn(buf[rr * 68 + cc] * z);
        }
    }
}

// ---------------------------------------------------------------------------
extern "C" void kernel_launch(void* const* d_in, const int* in_sizes, int n_in,
                              void* d_out, int out_size)
{
    const float* x  = (const float*)d_in[0];
    const float* Wq = (const float*)d_in[1];
    const float* bq = (const float*)d_in[2];
    const float* Wd = (const float*)d_in[3];
    const float* bd = (const float*)d_in[4];
    const float* Wu = (const float*)d_in[5];
    const float* bu = (const float*)d_in[6];
    const float* Wo = (const float*)d_in[7];
    const float* bo = (const float*)d_in[8];
    float* out = (float*)d_out;

    void *pXh, *pWfh, *pbqd, *pWuh, *pWoh, *pCh, *pOh;
    cudaGetSymbolAddress(&pXh,  g_Xh);
    cudaGetSymbolAddress(&pWfh, g_Wfh);
    cudaGetSymbolAddress(&pbqd, g_bqd);
    cudaGetSymbolAddress(&pWuh, g_Wuh);
    cudaGetSymbolAddress(&pWoh, g_Woh);
    cudaGetSymbolAddress(&pCh,  g_Ch);
    cudaGetSymbolAddress(&pOh,  g_Oh);

    cudaFuncSetAttribute(gemm_f16<0>, cudaFuncAttributeMaxDynamicSharedMemorySize, GEMM_SMEM);
    cudaFuncSetAttribute(gemm_f16<1>, cudaFuncAttributeMaxDynamicSharedMemorySize, GEMM_SMEM);
    cudaFuncSetAttribute(gemm_f16<2>, cudaFuncAttributeMaxDynamicSharedMemorySize, GEMM_SMEM);

    prep_kernel<<<PREP_BLOCKS, 256>>>(x, Wq, Wd, Wu, Wo, bq, bd);

    // [Q|C] = x @ [Wq|Wd] + [bq|bd], elu+1 on Q half.  grid: (N tiles, M tiles)
    gemm_f16<0><<<dim3(1280/BN, M_/BM), 256, GEMM_SMEM>>>(
        (const __half*)pXh, (const __half*)pWfh, (const float*)pbqd, nullptr, 1280, 1024);
    // KV = C@Wu + bu with FUSED ctx/ksum reduction (no KV materialization)
    gemm_f16<1><<<dim3(2048/BN, M_/BM), 256, GEMM_SMEM>>>(
        (const __half*)pCh, (const __half*)pWuh, bu, nullptr, 2048, 256);

    attn_out_kernel<<<dim3(64, 16), 128>>>();

    // out = O@Wo + bo
    gemm_f16<2><<<dim3(1024/BN, M_/BM), 256, GEMM_SMEM>>>(
        (const __half*)pOh, (const __half*)pWoh, bo, out, 1024, 1024);
}